// round 12
// baseline (speedup 1.0000x reference)
#include <cuda_runtime.h>
#include <cuda_fp16.h>
#include <math.h>
#include <stdint.h>

// ---------------- problem constants ----------------
#define NN 131072       // nodes
#define FF 768          // input features
#define HH 128          // hidden
#define BB 512          // graphs
#define NPG 256         // nodes per graph
#define EE 1048576      // directed edges (before symmetrization)
#define CC 4            // classes

// ---------------- scratch (device globals; no allocation) ----------------
__device__ float g_dinv[NN];
__device__ int   g_cnt[NN];
__device__ int   g_rowptr[NN + 1];
__device__ int   g_blksum[512];
__device__ int   g_cursor[NN];
__device__ int   g_esrc[2 * EE];

__device__ __align__(16) float g_h1pre[(size_t)NN * HH];   // X @ W1
__device__ __align__(16) float g_t2pre[(size_t)NN * HH];   // X @ W2a (+ h1 @ W2b)
__device__ __align__(16) float g_agg1[(size_t)NN * HH];    // conv1 out = h1 (relu'd)
__device__ __align__(16) float g_agg2[(size_t)NN * HH];    // conv2 out (pre-bias)
__device__ float g_pool1[BB * HH];
__device__ float g_pool2[BB * HH];
__device__ float g_root[BB * HH];

// fp16 transposed weights: [H=128 rows][K] row-major (K contiguous)
__device__ __align__(16) __half g_w1t[HH * FF];
__device__ __align__(16) __half g_w2at[HH * FF];
__device__ __align__(16) __half g_w2bt[HH * HH];

// ================= low-level helpers =================
__device__ __forceinline__ uint32_t smem_to_u32(const void* p) {
    uint32_t a;
    asm("{ .reg .u64 t; cvta.to.shared.u64 t, %1; cvt.u32.u64 %0, t; }"
        : "=r"(a) : "l"(p));
    return a;
}

__device__ __forceinline__ void cp16(uint32_t sdst, const void* gsrc) {
    asm volatile("cp.async.cg.shared.global [%0], [%1], 16;"
                 :: "r"(sdst), "l"(gsrc));
}
#define CP_COMMIT() asm volatile("cp.async.commit_group;" ::: "memory")
#define CP_WAIT0()  asm volatile("cp.async.wait_group 0;" ::: "memory")

__device__ __forceinline__ void ldmx4(uint32_t* r, uint32_t addr) {
    asm volatile("ldmatrix.sync.aligned.m8n8.x4.shared.b16 {%0,%1,%2,%3}, [%4];"
        : "=r"(r[0]), "=r"(r[1]), "=r"(r[2]), "=r"(r[3]) : "r"(addr));
}

__device__ __forceinline__ void mma16816(float* c, const uint32_t* a, const uint32_t* b) {
    asm volatile(
        "mma.sync.aligned.m16n8k16.row.col.f32.f16.f16.f32 "
        "{%0,%1,%2,%3}, {%4,%5,%6,%7}, {%8,%9}, {%0,%1,%2,%3};"
        : "+f"(c[0]), "+f"(c[1]), "+f"(c[2]), "+f"(c[3])
        : "r"(a[0]), "r"(a[1]), "r"(a[2]), "r"(a[3]), "r"(b[0]), "r"(b[1]));
}

__device__ __forceinline__ uint32_t pack_h2(__half a, __half b) {
    __half2 t; t.x = a; t.y = b;
    return *reinterpret_cast<uint32_t*>(&t);
}

// fp16 tile smem layout: 4 k16-blocks of [128 rows][32B]; stride 4128 + XOR swizzle.
#define BLKS  4128
#define TILE  16512          // one [128 x 64] fp16 tile (4 * BLKS)
__device__ __forceinline__ int swoff(int kb, int m, int c) {
    return kb * BLKS + m * 32 + ((c ^ ((m >> 2) & 1)) << 4);
}

// pipelined GEMM smem maps (single-pass fp16)
#define AR_OFF   0                         // raw fp32 A tile [128 x 64], 32768 B
#define ABF_OFF  32768                     // fp16 A tile (TILE bytes)
#define BB0_OFF  (ABF_OFF + TILE)          // 49280
#define X_SMEM   (BB0_OFF + 2 * 2 * TILE)  // 115328 (2 B tiles, double buffered)
#define H_SMEM   (BB0_OFF + 2 * 1 * TILE)  // 82304  (1 B tile,  double buffered)

// ---- cp.async: raw fp32 A tile -> AR staging ----
__device__ __forceinline__ void cpA(uint32_t sb, const float* __restrict__ A,
                                    int Ktot, int rowBase, int kc, int tid)
{
#pragma unroll
    for (int i = 0; i < 8; i++) {
        int f = i * 256 + tid;             // 2048 x 16B chunks
        int row = f >> 4, c = f & 15;
        cp16(sb + AR_OFF + row * 256 + c * 16,
             A + (size_t)(rowBase + row) * Ktot + kc * 64 + c * 4);
    }
}

// ---- convert AR (fp32) -> ABF (fp16, swizzled) ----
__device__ __forceinline__ void convert_AR(char* sm, int tid) {
#pragma unroll
    for (int i = 0; i < 8; i++) {
        int f = i * 256 + tid;
        int row = f >> 4, c = f & 15;
        float4 v = *reinterpret_cast<const float4*>(sm + AR_OFF + row * 256 + c * 16);
        int off = swoff(c >> 2, row, (c >> 1) & 1) + (c & 1) * 8;
        *reinterpret_cast<uint2*>(sm + ABF_OFF + off) =
            make_uint2(pack_h2(__float2half_rn(v.x), __float2half_rn(v.y)),
                       pack_h2(__float2half_rn(v.z), __float2half_rn(v.w)));
    }
}

// ---- fragment loaders ----
__device__ __forceinline__ void load_a_frags1(uint32_t abase, int ks, int wM, int lane,
                                              uint32_t ah[4][4])
{
#pragma unroll
    for (int mt = 0; mt < 4; mt++) {
        int r = wM + mt * 16 + (lane & 15);
        int c = lane >> 4;
        ldmx4(ah[mt], abase + (uint32_t)swoff(ks, r, c));
    }
}

__device__ __forceinline__ void load_b_frags(uint32_t bbase, int ks, int wN, int lane,
                                             uint32_t bf[4][2])
{
#pragma unroll
    for (int nt2 = 0; nt2 < 2; nt2++) {
        int n = wN + nt2 * 16 + (lane & 7) + ((lane >> 4) << 3);
        int c = (lane >> 3) & 1;
        uint32_t t[4];
        ldmx4(t, bbase + (uint32_t)swoff(ks, n, c));
        bf[nt2 * 2][0] = t[0]; bf[nt2 * 2][1] = t[1];
        bf[nt2 * 2 + 1][0] = t[2]; bf[nt2 * 2 + 1][1] = t[3];
    }
}

// ---- dual-output GEMM body: h1pre = X@W1^T, t2pre = X@W2a^T ----
__device__ __forceinline__ void mma_x2_body(const float* __restrict__ X,
                                            char* sm, int rowBase)
{
    const uint32_t sb = smem_to_u32(sm);
    const int tid = threadIdx.x;
    const int lane = tid & 31;
    const int wid = tid >> 5;
    const int wM = (wid & 1) * 64;
    const int wN = (wid >> 1) * 32;

    float acc1[4][4][4], acc2[4][4][4];
#pragma unroll
    for (int i = 0; i < 4; i++)
#pragma unroll
        for (int j = 0; j < 4; j++)
#pragma unroll
            for (int q = 0; q < 4; q++) { acc1[i][j][q] = 0.0f; acc2[i][j][q] = 0.0f; }

    cpA(sb, X, FF, rowBase, 0, tid);
#pragma unroll
    for (int it = 0; it < 4; it++) {
        int u = it * 256 + tid;
        int n = u >> 3, ch = u & 7;
        size_t go = (size_t)n * FF + ch * 8;
        int off = swoff(ch >> 1, n, ch & 1);
        cp16(sb + BB0_OFF + off,        g_w1t + go);
        cp16(sb + BB0_OFF + TILE + off, g_w2at + go);
    }
    CP_COMMIT();

    for (int kc = 0; kc < FF / 64; kc++) {
        CP_WAIT0();
        __syncthreads();
        convert_AR(sm, tid);
        __syncthreads();

        if (kc + 1 < FF / 64) {
            cpA(sb, X, FF, rowBase, kc + 1, tid);
            uint32_t bdst = sb + BB0_OFF + (uint32_t)(((kc + 1) & 1) * 2 * TILE);
#pragma unroll
            for (int it = 0; it < 4; it++) {
                int u = it * 256 + tid;
                int n = u >> 3, ch = u & 7;
                size_t go = (size_t)n * FF + (kc + 1) * 64 + ch * 8;
                int off = swoff(ch >> 1, n, ch & 1);
                cp16(bdst + off,        g_w1t + go);
                cp16(bdst + TILE + off, g_w2at + go);
            }
            CP_COMMIT();
        }

        uint32_t bbB = sb + BB0_OFF + (uint32_t)((kc & 1) * 2 * TILE);
#pragma unroll
        for (int ks = 0; ks < 4; ks++) {
            uint32_t ah[4][4];
            load_a_frags1(sb + ABF_OFF, ks, wM, lane, ah);
            {
                uint32_t bh[4][2];
                load_b_frags(bbB, ks, wN, lane, bh);
#pragma unroll
                for (int mt = 0; mt < 4; mt++)
#pragma unroll
                    for (int nt = 0; nt < 4; nt++)
                        mma16816(acc1[mt][nt], ah[mt], bh[nt]);
            }
            {
                uint32_t bh[4][2];
                load_b_frags(bbB + TILE, ks, wN, lane, bh);
#pragma unroll
                for (int mt = 0; mt < 4; mt++)
#pragma unroll
                    for (int nt = 0; nt < 4; nt++)
                        mma16816(acc2[mt][nt], ah[mt], bh[nt]);
            }
        }
    }

#pragma unroll
    for (int mt = 0; mt < 4; mt++) {
        int row = rowBase + wM + mt * 16 + (lane >> 2);
#pragma unroll
        for (int nt = 0; nt < 4; nt++) {
            int col = wN + nt * 8 + (lane & 3) * 2;
            *reinterpret_cast<float2*>(&g_h1pre[(size_t)row * HH + col]) =
                make_float2(acc1[mt][nt][0], acc1[mt][nt][1]);
            *reinterpret_cast<float2*>(&g_h1pre[(size_t)(row + 8) * HH + col]) =
                make_float2(acc1[mt][nt][2], acc1[mt][nt][3]);
            *reinterpret_cast<float2*>(&g_t2pre[(size_t)row * HH + col]) =
                make_float2(acc2[mt][nt][0], acc2[mt][nt][1]);
            *reinterpret_cast<float2*>(&g_t2pre[(size_t)(row + 8) * HH + col]) =
                make_float2(acc2[mt][nt][2], acc2[mt][nt][3]);
        }
    }
}

// ---- accumulating GEMM body: t2pre += h1 @ W2b^T (K = 128) ----
__device__ __forceinline__ void mma_h_body(const float* __restrict__ A,
                                           char* sm, int rowBase)
{
    const uint32_t sb = smem_to_u32(sm);
    const int tid = threadIdx.x;
    const int lane = tid & 31;
    const int wid = tid >> 5;
    const int wM = (wid & 1) * 64;
    const int wN = (wid >> 1) * 32;

    float acc[4][4][4];
#pragma unroll
    for (int i = 0; i < 4; i++)
#pragma unroll
        for (int j = 0; j < 4; j++)
#pragma unroll
            for (int q = 0; q < 4; q++) acc[i][j][q] = 0.0f;

    cpA(sb, A, HH, rowBase, 0, tid);
#pragma unroll
    for (int it = 0; it < 4; it++) {
        int u = it * 256 + tid;
        int n = u >> 3, ch = u & 7;
        size_t go = (size_t)n * HH + ch * 8;
        int off = swoff(ch >> 1, n, ch & 1);
        cp16(sb + BB0_OFF + off, g_w2bt + go);
    }
    CP_COMMIT();

    for (int kc = 0; kc < 2; kc++) {
        CP_WAIT0();
        __syncthreads();
        convert_AR(sm, tid);
        __syncthreads();

        if (kc == 0) {
            cpA(sb, A, HH, rowBase, 1, tid);
            uint32_t bdst = sb + BB0_OFF + TILE;
#pragma unroll
            for (int it = 0; it < 4; it++) {
                int u = it * 256 + tid;
                int n = u >> 3, ch = u & 7;
                size_t go = (size_t)n * HH + 64 + ch * 8;
                int off = swoff(ch >> 1, n, ch & 1);
                cp16(bdst + off, g_w2bt + go);
            }
            CP_COMMIT();
        }

        uint32_t bbB = sb + BB0_OFF + (uint32_t)(kc * TILE);
#pragma unroll
        for (int ks = 0; ks < 4; ks++) {
            uint32_t ah[4][4];
            load_a_frags1(sb + ABF_OFF, ks, wM, lane, ah);
            uint32_t bh[4][2];
            load_b_frags(bbB, ks, wN, lane, bh);
#pragma unroll
            for (int mt = 0; mt < 4; mt++)
#pragma unroll
                for (int nt = 0; nt < 4; nt++)
                    mma16816(acc[mt][nt], ah[mt], bh[nt]);
        }
    }

#pragma unroll
    for (int mt = 0; mt < 4; mt++) {
        int row = rowBase + wM + mt * 16 + (lane >> 2);
#pragma unroll
        for (int nt = 0; nt < 4; nt++) {
            int col = wN + nt * 8 + (lane & 3) * 2;
            float2* p0 = reinterpret_cast<float2*>(&g_t2pre[(size_t)row * HH + col]);
            float2* p1 = reinterpret_cast<float2*>(&g_t2pre[(size_t)(row + 8) * HH + col]);
            float2 e0 = *p0, e1 = *p1;
            *p0 = make_float2(acc[mt][nt][0] + e0.x, acc[mt][nt][1] + e0.y);
            *p1 = make_float2(acc[mt][nt][2] + e1.x, acc[mt][nt][3] + e1.y);
        }
    }
}

// ---------------- small setup kernels ----------------
__global__ void k_zero_cnt() {
    int i = blockIdx.x * blockDim.x + threadIdx.x;
    if (i < NN) g_cnt[i] = 0;
}

// FAT1: blocks [0,384) = wprep; [384, 8576) = deg_count
__global__ void k_fat1(const int* __restrict__ ei,
                       const float* __restrict__ W1, const float* __restrict__ W2)
{
    int bid = blockIdx.x;
    if (bid < 384) {
        int t = bid * 256 + threadIdx.x;
        if (t >= HH * FF) return;
        int h = t / FF, k = t % FF;
        g_w1t[t]  = __float2half_rn(W1[(size_t)k * HH + h]);
        g_w2at[t] = __float2half_rn(W2[(size_t)k * HH + h]);
        if (t < HH * HH) {
            int h2 = t / HH, k2 = t % HH;
            g_w2bt[t] = __float2half_rn(W2[(size_t)(FF + k2) * HH + h2]);
        }
        return;
    }
    int t = (bid - 384) * 256 + threadIdx.x;
    if (t < 2 * EE) atomicAdd(&g_cnt[__ldg(&ei[t])], 1);
}

// scan1 with fused deg_fin (dinv + cursor init)
__global__ void k_scan1() {
    __shared__ int sh[256];
    int tid = threadIdx.x;
    int i = blockIdx.x * 256 + tid;
    int v = g_cnt[i];
    g_dinv[i] = rsqrtf((float)v + 1.0f);   // +1 self loop
    g_cursor[i] = 0;
    sh[tid] = v;
    __syncthreads();
#pragma unroll
    for (int o = 1; o < 256; o <<= 1) {
        int t = (tid >= o) ? sh[tid - o] : 0;
        __syncthreads();
        sh[tid] += t;
        __syncthreads();
    }
    g_rowptr[i] = sh[tid] - v;
    if (tid == 255) g_blksum[blockIdx.x] = sh[255];
}

__global__ void k_scan2() {
    __shared__ int sh[512];
    int tid = threadIdx.x;
    int v = g_blksum[tid];
    sh[tid] = v;
    __syncthreads();
#pragma unroll
    for (int o = 1; o < 512; o <<= 1) {
        int t = (tid >= o) ? sh[tid - o] : 0;
        __syncthreads();
        sh[tid] += t;
        __syncthreads();
    }
    g_blksum[tid] = sh[tid] - v;
}

__global__ void k_scan3() {
    int i = blockIdx.x * 256 + threadIdx.x;
    g_rowptr[i] += g_blksum[blockIdx.x];
    if (i == NN - 1) g_rowptr[NN] = 2 * EE;
}

// ---------------- FAT2: fill ∪ root ∪ mma_x2 ----------------
// blocks [0,256): CSR fill (grid-stride); [256,512): root (2 graphs/block);
// [512,1536): dual-output GEMM.
__global__ void __launch_bounds__(256, 1) k_fat2(
    const float* __restrict__ X, const int* __restrict__ ei,
    const float* __restrict__ Wr, const float* __restrict__ br)
{
    extern __shared__ char sm[];
    int bid = blockIdx.x;

    if (bid < 256) {                        // CSR fill
        for (int t = bid * 256 + threadIdx.x; t < 2 * EE; t += 256 * 256) {
            int src = __ldg(&ei[t]);
            int dst = (t < EE) ? __ldg(&ei[t + EE]) : __ldg(&ei[t - EE]);
            int pos = g_rowptr[dst] + atomicAdd(&g_cursor[dst], 1);
            g_esrc[pos] = src;
        }
        return;
    }
    if (bid < 512) {                        // root transform, 2 graphs per block
        float* xs = reinterpret_cast<float*>(sm) + (threadIdx.x >> 7) * FF;
        int g = (bid - 256) * 2 + (threadIdx.x >> 7);
        int j = threadIdx.x & 127;
        const float* xr = X + (size_t)g * NPG * FF;
        for (int k = j; k < FF; k += 128) xs[k] = xr[k];
        __syncthreads();
        float acc = __ldg(&br[j]);
#pragma unroll 8
        for (int k = 0; k < FF; k++)
            acc = fmaf(xs[k], __ldg(&Wr[(size_t)k * HH + j]), acc);
        g_root[g * HH + j] = fmaxf(acc, 0.0f);
        return;
    }
    mma_x2_body(X, sm, (bid - 512) * 128);  // GEMM
}

// ---------------- FAT3: pool1 ∪ mma_h ----------------
// blocks [0,256): pool1 (2 graphs/block); [256,1280): mma_h.
__global__ void __launch_bounds__(256, 1) k_fat3(const float* __restrict__ agg1)
{
    extern __shared__ char sm[];
    int bid = blockIdx.x;
    if (bid < 256) {                        // pool1 = segment_max(h1)
        int g = bid * 2 + (threadIdx.x >> 7);
        int j = threadIdx.x & 127;
        const float* p = agg1 + (size_t)g * NPG * HH + j;
        float m = -INFINITY;
#pragma unroll 8
        for (int n = 0; n < NPG; n++) m = fmaxf(m, p[(size_t)n * HH]);
        g_pool1[g * HH + j] = m;
        return;
    }
    mma_h_body(agg1, sm, (bid - 256) * 128);
}

// ---------------- pull-based propagation (no atomics) ----------------
template <bool RELU>
__global__ void __launch_bounds__(256) k_prop_csr(const float* __restrict__ h,
                                                  float* __restrict__ agg,
                                                  const float* __restrict__ bias)
{
    int node = blockIdx.x * 8 + (threadIdx.x >> 5);
    int lane = threadIdx.x & 31;
    const float4* h4 = reinterpret_cast<const float4*>(h);
    float dn = __ldg(&g_dinv[node]);
    float4 acc = __ldg(&h4[(size_t)node * 32 + lane]);
    float s2 = dn * dn;
    acc.x *= s2; acc.y *= s2; acc.z *= s2; acc.w *= s2;
    int start = __ldg(&g_rowptr[node]);
    int end   = __ldg(&g_rowptr[node + 1]);
    for (int base = start; base < end; base += 32) {
        int n = min(32, end - base);
        int si = (base + lane < end) ? __ldg(&g_esrc[base + lane]) : 0;
#pragma unroll 4
        for (int j = 0; j < n; j++) {
            int s = __shfl_sync(0xffffffffu, si, j);
            float w = __ldg(&g_dinv[s]) * dn;
            float4 v = __ldg(&h4[(size_t)s * 32 + lane]);
            acc.x = fmaf(v.x, w, acc.x);
            acc.y = fmaf(v.y, w, acc.y);
            acc.z = fmaf(v.z, w, acc.z);
            acc.w = fmaf(v.w, w, acc.w);
        }
    }
    if (RELU) {
        float4 b = *reinterpret_cast<const float4*>(bias + lane * 4);
        acc.x = fmaxf(acc.x + b.x, 0.0f);
        acc.y = fmaxf(acc.y + b.y, 0.0f);
        acc.z = fmaxf(acc.z + b.z, 0.0f);
        acc.w = fmaxf(acc.w + b.w, 0.0f);
    }
    reinterpret_cast<float4*>(agg)[(size_t)node * 32 + lane] = acc;
}

// ---------------- segment max with bias ----------------
__global__ void k_poolmax(const float* __restrict__ h, const float* __restrict__ bias,
                          float* __restrict__ out)
{
    int g = blockIdx.x, j = threadIdx.x;
    const float* p = h + (size_t)g * NPG * HH + j;
    float m = -INFINITY;
#pragma unroll 8
    for (int n = 0; n < NPG; n++) m = fmaxf(m, p[(size_t)n * HH]);
    m += __ldg(&bias[j]);
    out[g * HH + j] = m;
}

// ---------------- head (+ arange tail) ----------------
__global__ void k_head(const float* __restrict__ pool2, const float* __restrict__ Wl,
                       const float* __restrict__ bl, float* __restrict__ out, int extra)
{
    if (blockIdx.x >= BB / 8) {             // tail: idx = arange(B) as floats
        int t = (blockIdx.x - BB / 8) * 256 + threadIdx.x;
        if (t < extra) out[BB * CC + t] = (float)t;
        return;
    }
    int g = blockIdx.x * 8 + (threadIdx.x >> 5);
    int lane = threadIdx.x & 31;
    float a0 = 0.f, a1 = 0.f, a2 = 0.f, a3 = 0.f;
    for (int k = lane; k < 3 * HH; k += 32) {
        float v = (k < HH) ? g_root[g * HH + k]
                : (k < 2 * HH) ? pool2[g * HH + k - HH]
                : g_pool1[g * HH + k - 2 * HH];
        float4 w = __ldg(reinterpret_cast<const float4*>(Wl) + k);
        a0 = fmaf(v, w.x, a0); a1 = fmaf(v, w.y, a1);
        a2 = fmaf(v, w.z, a2); a3 = fmaf(v, w.w, a3);
    }
#pragma unroll
    for (int o = 16; o > 0; o >>= 1) {
        a0 += __shfl_xor_sync(0xffffffffu, a0, o);
        a1 += __shfl_xor_sync(0xffffffffu, a1, o);
        a2 += __shfl_xor_sync(0xffffffffu, a2, o);
        a3 += __shfl_xor_sync(0xffffffffu, a3, o);
    }
    if (lane == 0) {
        float l0 = a0 + __ldg(&bl[0]);
        float l1 = a1 + __ldg(&bl[1]);
        float l2 = a2 + __ldg(&bl[2]);
        float l3 = a3 + __ldg(&bl[3]);
        float m = fmaxf(fmaxf(l0, l1), fmaxf(l2, l3));
        float s = expf(l0 - m) + expf(l1 - m) + expf(l2 - m) + expf(l3 - m);
        float lse = m + logf(s);
        out[g * CC + 0] = l0 - lse;
        out[g * CC + 1] = l1 - lse;
        out[g * CC + 2] = l2 - lse;
        out[g * CC + 3] = l3 - lse;
    }
}

// ---------------- launch ----------------
extern "C" void kernel_launch(void* const* d_in, const int* in_sizes, int n_in,
                              void* d_out, int out_size)
{
    const float* x  = (const float*)d_in[0];
    const int*   ei = (const int*)d_in[1];
    const float* W1 = (const float*)d_in[3];
    const float* b1 = (const float*)d_in[4];
    const float* W2 = (const float*)d_in[5];
    const float* b2 = (const float*)d_in[6];
    const float* Wr = (const float*)d_in[7];
    const float* br = (const float*)d_in[8];
    const float* Wl = (const float*)d_in[9];
    const float* bl = (const float*)d_in[10];
    float* out = (float*)d_out;

    float *h1pre, *t2pre, *agg1, *agg2, *pool2;
    cudaGetSymbolAddress((void**)&h1pre, g_h1pre);
    cudaGetSymbolAddress((void**)&t2pre, g_t2pre);
    cudaGetSymbolAddress((void**)&agg1,  g_agg1);
    cudaGetSymbolAddress((void**)&agg2,  g_agg2);
    cudaGetSymbolAddress((void**)&pool2, g_pool2);

    cudaFuncSetAttribute(k_fat2, cudaFuncAttributeMaxDynamicSharedMemorySize, X_SMEM);
    cudaFuncSetAttribute(k_fat3, cudaFuncAttributeMaxDynamicSharedMemorySize, H_SMEM);

    // 1) zero counters; FAT1 = degree count ∪ weight prep
    k_zero_cnt<<<NN / 256, 256>>>();
    k_fat1<<<384 + (2 * EE) / 256, 256>>>(ei, W1, W2);

    // 2) rowptr scan (deg_fin fused into scan1)
    k_scan1<<<512, 256>>>();
    k_scan2<<<1, 512>>>();
    k_scan3<<<512, 256>>>();

    // 3) FAT2 = CSR fill ∪ root transform ∪ dual-output GEMM
    k_fat2<<<512 + NN / 128, 256, X_SMEM>>>(x, ei, Wr, br);

    // 4) conv1 propagate + fused bias/relu -> agg1 = h1
    k_prop_csr<true><<<NN / 8, 256>>>(h1pre, agg1, b1);

    // 5) FAT3 = pool1 ∪ (t2pre += h1 @ W2b)
    k_fat3<<<256 + NN / 128, 256, H_SMEM>>>(agg1);

    // 6) conv2 propagate; pool2 = segment_max(agg2) + b2
    k_prop_csr<false><<<NN / 8, 256>>>(t2pre, agg2, nullptr);
    k_poolmax<<<BB, HH>>>(agg2, b2, pool2);

    // 7) head + tail
    int extra = out_size - BB * CC;
    int tailBlocks = (extra > 0) ? (extra + 255) / 256 : 0;
    k_head<<<BB / 8 + tailBlocks, 256>>>(pool2, Wl, bl, out, extra);
}

// round 13
// speedup vs baseline: 1.0743x; 1.0743x over previous
#include <cuda_runtime.h>
#include <cuda_fp16.h>
#include <math.h>
#include <stdint.h>

// ---------------- problem constants ----------------
#define NN 131072       // nodes
#define FF 768          // input features
#define HH 128          // hidden
#define BB 512          // graphs
#define NPG 256         // nodes per graph
#define EE 1048576      // directed edges (before symmetrization)
#define CC 4            // classes

// ---------------- scratch (device globals; no allocation) ----------------
__device__ float g_dinv[NN];
__device__ int   g_cnt[NN];
__device__ int   g_rowptr[NN + 1];
__device__ int   g_blksum[512];
__device__ int   g_cursor[NN];
__device__ int   g_esrc[2 * EE];

__device__ __align__(16) float g_h1pre[(size_t)NN * HH];   // X @ W1
__device__ __align__(16) float g_t2pre[(size_t)NN * HH];   // X @ W2a (+ h1 @ W2b)
__device__ __align__(16) float g_agg1[(size_t)NN * HH];    // conv1 out = h1 (relu'd)
__device__ __align__(16) float g_agg2[(size_t)NN * HH];    // conv2 out (pre-bias)
__device__ float g_pool1[BB * HH];
__device__ float g_pool2[BB * HH];
__device__ float g_root[BB * HH];

// fp16 transposed weights: [H=128 rows][K] row-major (K contiguous)
__device__ __align__(16) __half g_w1t[HH * FF];
__device__ __align__(16) __half g_w2at[HH * FF];
__device__ __align__(16) __half g_w2bt[HH * HH];

// ================= low-level helpers =================
__device__ __forceinline__ uint32_t smem_to_u32(const void* p) {
    uint32_t a;
    asm("{ .reg .u64 t; cvta.to.shared.u64 t, %1; cvt.u32.u64 %0, t; }"
        : "=r"(a) : "l"(p));
    return a;
}

__device__ __forceinline__ void cp16(uint32_t sdst, const void* gsrc) {
    asm volatile("cp.async.cg.shared.global [%0], [%1], 16;"
                 :: "r"(sdst), "l"(gsrc));
}
#define CP_COMMIT() asm volatile("cp.async.commit_group;" ::: "memory")
#define CP_WAIT0()  asm volatile("cp.async.wait_group 0;" ::: "memory")

__device__ __forceinline__ void ldmx4(uint32_t* r, uint32_t addr) {
    asm volatile("ldmatrix.sync.aligned.m8n8.x4.shared.b16 {%0,%1,%2,%3}, [%4];"
        : "=r"(r[0]), "=r"(r[1]), "=r"(r[2]), "=r"(r[3]) : "r"(addr));
}

__device__ __forceinline__ void mma16816(float* c, const uint32_t* a, const uint32_t* b) {
    asm volatile(
        "mma.sync.aligned.m16n8k16.row.col.f32.f16.f16.f32 "
        "{%0,%1,%2,%3}, {%4,%5,%6,%7}, {%8,%9}, {%0,%1,%2,%3};"
        : "+f"(c[0]), "+f"(c[1]), "+f"(c[2]), "+f"(c[3])
        : "r"(a[0]), "r"(a[1]), "r"(a[2]), "r"(a[3]), "r"(b[0]), "r"(b[1]));
}

__device__ __forceinline__ uint32_t pack_h2(__half a, __half b) {
    __half2 t; t.x = a; t.y = b;
    return *reinterpret_cast<uint32_t*>(&t);
}

// fp16 tile smem layout: 4 k16-blocks of [128 rows][32B]; stride 4128 + XOR swizzle.
#define BLKS  4128
#define TILE  16512          // one [128 x 64] fp16 tile (4 * BLKS)
__device__ __forceinline__ int swoff(int kb, int m, int c) {
    return kb * BLKS + m * 32 + ((c ^ ((m >> 2) & 1)) << 4);
}

// pipelined GEMM smem maps (single-pass fp16)
#define AR_OFF   0                         // raw fp32 A tile [128 x 64], 32768 B
#define ABF_OFF  32768                     // fp16 A tile (TILE bytes)
#define BB0_OFF  (ABF_OFF + TILE)          // 49280
#define X_SMEM   (BB0_OFF + 2 * 2 * TILE)  // 115328 (2 B tiles, double buffered)
#define H_SMEM   (BB0_OFF + 2 * 1 * TILE)  // 82304  (1 B tile,  double buffered)

// ---- cp.async: raw fp32 A tile -> AR staging ----
__device__ __forceinline__ void cpA(uint32_t sb, const float* __restrict__ A,
                                    int Ktot, int rowBase, int kc, int tid)
{
#pragma unroll
    for (int i = 0; i < 8; i++) {
        int f = i * 256 + tid;             // 2048 x 16B chunks
        int row = f >> 4, c = f & 15;
        cp16(sb + AR_OFF + row * 256 + c * 16,
             A + (size_t)(rowBase + row) * Ktot + kc * 64 + c * 4);
    }
}

// ---- convert AR (fp32) -> ABF (fp16, swizzled) ----
__device__ __forceinline__ void convert_AR(char* sm, int tid) {
#pragma unroll
    for (int i = 0; i < 8; i++) {
        int f = i * 256 + tid;
        int row = f >> 4, c = f & 15;
        float4 v = *reinterpret_cast<const float4*>(sm + AR_OFF + row * 256 + c * 16);
        int off = swoff(c >> 2, row, (c >> 1) & 1) + (c & 1) * 8;
        *reinterpret_cast<uint2*>(sm + ABF_OFF + off) =
            make_uint2(pack_h2(__float2half_rn(v.x), __float2half_rn(v.y)),
                       pack_h2(__float2half_rn(v.z), __float2half_rn(v.w)));
    }
}

// ---- fragment loaders ----
__device__ __forceinline__ void load_a_frags1(uint32_t abase, int ks, int wM, int lane,
                                              uint32_t ah[4][4])
{
#pragma unroll
    for (int mt = 0; mt < 4; mt++) {
        int r = wM + mt * 16 + (lane & 15);
        int c = lane >> 4;
        ldmx4(ah[mt], abase + (uint32_t)swoff(ks, r, c));
    }
}

__device__ __forceinline__ void load_b_frags(uint32_t bbase, int ks, int wN, int lane,
                                             uint32_t bf[4][2])
{
#pragma unroll
    for (int nt2 = 0; nt2 < 2; nt2++) {
        int n = wN + nt2 * 16 + (lane & 7) + ((lane >> 4) << 3);
        int c = (lane >> 3) & 1;
        uint32_t t[4];
        ldmx4(t, bbase + (uint32_t)swoff(ks, n, c));
        bf[nt2 * 2][0] = t[0]; bf[nt2 * 2][1] = t[1];
        bf[nt2 * 2 + 1][0] = t[2]; bf[nt2 * 2 + 1][1] = t[3];
    }
}

// ======= pipelined dual-output GEMM: h1pre = X@W1^T, t2pre = X@W2a^T =======
__global__ void __launch_bounds__(256, 1) k_mma_x2(const float* __restrict__ X) {
    extern __shared__ char sm[];
    const uint32_t sb = smem_to_u32(sm);
    const int tid = threadIdx.x;
    const int lane = tid & 31;
    const int wid = tid >> 5;
    const int wM = (wid & 1) * 64;
    const int wN = (wid >> 1) * 32;
    const int rowBase = blockIdx.x * 128;

    float acc1[4][4][4], acc2[4][4][4];
#pragma unroll
    for (int i = 0; i < 4; i++)
#pragma unroll
        for (int j = 0; j < 4; j++)
#pragma unroll
            for (int q = 0; q < 4; q++) { acc1[i][j][q] = 0.0f; acc2[i][j][q] = 0.0f; }

    cpA(sb, X, FF, rowBase, 0, tid);
#pragma unroll
    for (int it = 0; it < 4; it++) {
        int u = it * 256 + tid;
        int n = u >> 3, ch = u & 7;
        size_t go = (size_t)n * FF + ch * 8;
        int off = swoff(ch >> 1, n, ch & 1);
        cp16(sb + BB0_OFF + off,        g_w1t + go);
        cp16(sb + BB0_OFF + TILE + off, g_w2at + go);
    }
    CP_COMMIT();

    for (int kc = 0; kc < FF / 64; kc++) {
        CP_WAIT0();
        __syncthreads();
        convert_AR(sm, tid);
        __syncthreads();

        if (kc + 1 < FF / 64) {
            cpA(sb, X, FF, rowBase, kc + 1, tid);
            uint32_t bdst = sb + BB0_OFF + (uint32_t)(((kc + 1) & 1) * 2 * TILE);
#pragma unroll
            for (int it = 0; it < 4; it++) {
                int u = it * 256 + tid;
                int n = u >> 3, ch = u & 7;
                size_t go = (size_t)n * FF + (kc + 1) * 64 + ch * 8;
                int off = swoff(ch >> 1, n, ch & 1);
                cp16(bdst + off,        g_w1t + go);
                cp16(bdst + TILE + off, g_w2at + go);
            }
            CP_COMMIT();
        }

        uint32_t bbB = sb + BB0_OFF + (uint32_t)((kc & 1) * 2 * TILE);
#pragma unroll
        for (int ks = 0; ks < 4; ks++) {
            uint32_t ah[4][4];
            load_a_frags1(sb + ABF_OFF, ks, wM, lane, ah);
            {
                uint32_t bh[4][2];
                load_b_frags(bbB, ks, wN, lane, bh);
#pragma unroll
                for (int mt = 0; mt < 4; mt++)
#pragma unroll
                    for (int nt = 0; nt < 4; nt++)
                        mma16816(acc1[mt][nt], ah[mt], bh[nt]);
            }
            {
                uint32_t bh[4][2];
                load_b_frags(bbB + TILE, ks, wN, lane, bh);
#pragma unroll
                for (int mt = 0; mt < 4; mt++)
#pragma unroll
                    for (int nt = 0; nt < 4; nt++)
                        mma16816(acc2[mt][nt], ah[mt], bh[nt]);
            }
        }
    }

#pragma unroll
    for (int mt = 0; mt < 4; mt++) {
        int row = rowBase + wM + mt * 16 + (lane >> 2);
#pragma unroll
        for (int nt = 0; nt < 4; nt++) {
            int col = wN + nt * 8 + (lane & 3) * 2;
            *reinterpret_cast<float2*>(&g_h1pre[(size_t)row * HH + col]) =
                make_float2(acc1[mt][nt][0], acc1[mt][nt][1]);
            *reinterpret_cast<float2*>(&g_h1pre[(size_t)(row + 8) * HH + col]) =
                make_float2(acc1[mt][nt][2], acc1[mt][nt][3]);
            *reinterpret_cast<float2*>(&g_t2pre[(size_t)row * HH + col]) =
                make_float2(acc2[mt][nt][0], acc2[mt][nt][1]);
            *reinterpret_cast<float2*>(&g_t2pre[(size_t)(row + 8) * HH + col]) =
                make_float2(acc2[mt][nt][2], acc2[mt][nt][3]);
        }
    }
}

// ======= pipelined accumulating GEMM: t2pre += h1 @ W2b^T (K = 128) =======
__global__ void __launch_bounds__(256, 1) k_mma_h(const float* __restrict__ A) {
    extern __shared__ char sm[];
    const uint32_t sb = smem_to_u32(sm);
    const int tid = threadIdx.x;
    const int lane = tid & 31;
    const int wid = tid >> 5;
    const int wM = (wid & 1) * 64;
    const int wN = (wid >> 1) * 32;
    const int rowBase = blockIdx.x * 128;

    float acc[4][4][4];
#pragma unroll
    for (int i = 0; i < 4; i++)
#pragma unroll
        for (int j = 0; j < 4; j++)
#pragma unroll
            for (int q = 0; q < 4; q++) acc[i][j][q] = 0.0f;

    cpA(sb, A, HH, rowBase, 0, tid);
#pragma unroll
    for (int it = 0; it < 4; it++) {
        int u = it * 256 + tid;
        int n = u >> 3, ch = u & 7;
        size_t go = (size_t)n * HH + ch * 8;
        int off = swoff(ch >> 1, n, ch & 1);
        cp16(sb + BB0_OFF + off, g_w2bt + go);
    }
    CP_COMMIT();

    for (int kc = 0; kc < 2; kc++) {
        CP_WAIT0();
        __syncthreads();
        convert_AR(sm, tid);
        __syncthreads();

        if (kc == 0) {
            cpA(sb, A, HH, rowBase, 1, tid);
            uint32_t bdst = sb + BB0_OFF + TILE;
#pragma unroll
            for (int it = 0; it < 4; it++) {
                int u = it * 256 + tid;
                int n = u >> 3, ch = u & 7;
                size_t go = (size_t)n * HH + 64 + ch * 8;
                int off = swoff(ch >> 1, n, ch & 1);
                cp16(bdst + off, g_w2bt + go);
            }
            CP_COMMIT();
        }

        uint32_t bbB = sb + BB0_OFF + (uint32_t)(kc * TILE);
#pragma unroll
        for (int ks = 0; ks < 4; ks++) {
            uint32_t ah[4][4];
            load_a_frags1(sb + ABF_OFF, ks, wM, lane, ah);
            uint32_t bh[4][2];
            load_b_frags(bbB, ks, wN, lane, bh);
#pragma unroll
            for (int mt = 0; mt < 4; mt++)
#pragma unroll
                for (int nt = 0; nt < 4; nt++)
                    mma16816(acc[mt][nt], ah[mt], bh[nt]);
        }
    }

#pragma unroll
    for (int mt = 0; mt < 4; mt++) {
        int row = rowBase + wM + mt * 16 + (lane >> 2);
#pragma unroll
        for (int nt = 0; nt < 4; nt++) {
            int col = wN + nt * 8 + (lane & 3) * 2;
            float2* p0 = reinterpret_cast<float2*>(&g_t2pre[(size_t)row * HH + col]);
            float2* p1 = reinterpret_cast<float2*>(&g_t2pre[(size_t)(row + 8) * HH + col]);
            float2 e0 = *p0, e1 = *p1;
            *p0 = make_float2(acc[mt][nt][0] + e0.x, acc[mt][nt][1] + e0.y);
            *p1 = make_float2(acc[mt][nt][2] + e1.x, acc[mt][nt][3] + e1.y);
        }
    }
}

// ---------------- weight prep: transpose to fp16 ----------------
__global__ void k_wprep(const float* __restrict__ W1, const float* __restrict__ W2) {
    int t = blockIdx.x * blockDim.x + threadIdx.x;
    if (t >= HH * FF) return;
    int h = t / FF, k = t % FF;
    g_w1t[t]  = __float2half_rn(W1[(size_t)k * HH + h]);
    g_w2at[t] = __float2half_rn(W2[(size_t)k * HH + h]);
    if (t < HH * HH) {
        int h2 = t / HH, k2 = t % HH;
        g_w2bt[t] = __float2half_rn(W2[(size_t)(FF + k2) * HH + h2]);
    }
}

// ---------------- degree / CSR build ----------------
__global__ void k_zero_cnt() {
    int i = blockIdx.x * blockDim.x + threadIdx.x;
    if (i < NN) g_cnt[i] = 0;
}

__global__ void k_deg_count(const int* __restrict__ ei) {
    int t = blockIdx.x * blockDim.x + threadIdx.x;
    if (t < 2 * EE) atomicAdd(&g_cnt[__ldg(&ei[t])], 1);
}

// scan1 with fused deg_fin (dinv + cursor init)
__global__ void k_scan1() {
    __shared__ int sh[256];
    int tid = threadIdx.x;
    int i = blockIdx.x * 256 + tid;
    int v = g_cnt[i];
    g_dinv[i] = rsqrtf((float)v + 1.0f);   // +1 self loop
    g_cursor[i] = 0;
    sh[tid] = v;
    __syncthreads();
#pragma unroll
    for (int o = 1; o < 256; o <<= 1) {
        int t = (tid >= o) ? sh[tid - o] : 0;
        __syncthreads();
        sh[tid] += t;
        __syncthreads();
    }
    g_rowptr[i] = sh[tid] - v;
    if (tid == 255) g_blksum[blockIdx.x] = sh[255];
}

__global__ void k_scan2() {
    __shared__ int sh[512];
    int tid = threadIdx.x;
    int v = g_blksum[tid];
    sh[tid] = v;
    __syncthreads();
#pragma unroll
    for (int o = 1; o < 512; o <<= 1) {
        int t = (tid >= o) ? sh[tid - o] : 0;
        __syncthreads();
        sh[tid] += t;
        __syncthreads();
    }
    g_blksum[tid] = sh[tid] - v;
}

__global__ void k_scan3() {
    int i = blockIdx.x * 256 + threadIdx.x;
    g_rowptr[i] += g_blksum[blockIdx.x];
    if (i == NN - 1) g_rowptr[NN] = 2 * EE;
}

__global__ void k_fill(const int* __restrict__ ei) {
    int t = blockIdx.x * blockDim.x + threadIdx.x;
    if (t >= 2 * EE) return;
    int src = __ldg(&ei[t]);
    int dst = (t < EE) ? __ldg(&ei[t + EE]) : __ldg(&ei[t - EE]);
    int pos = g_rowptr[dst] + atomicAdd(&g_cursor[dst], 1);
    g_esrc[pos] = src;
}

// ---------------- pull-based propagation (no atomics) ----------------
template <bool RELU>
__global__ void __launch_bounds__(256) k_prop_csr(const float* __restrict__ h,
                                                  float* __restrict__ agg,
                                                  const float* __restrict__ bias)
{
    int node = blockIdx.x * 8 + (threadIdx.x >> 5);
    int lane = threadIdx.x & 31;
    const float4* h4 = reinterpret_cast<const float4*>(h);
    float dn = __ldg(&g_dinv[node]);
    float4 acc = __ldg(&h4[(size_t)node * 32 + lane]);
    float s2 = dn * dn;
    acc.x *= s2; acc.y *= s2; acc.z *= s2; acc.w *= s2;
    int start = __ldg(&g_rowptr[node]);
    int end   = __ldg(&g_rowptr[node + 1]);
    for (int base = start; base < end; base += 32) {
        int n = min(32, end - base);
        int si = (base + lane < end) ? __ldg(&g_esrc[base + lane]) : 0;
#pragma unroll 4
        for (int j = 0; j < n; j++) {
            int s = __shfl_sync(0xffffffffu, si, j);
            float w = __ldg(&g_dinv[s]) * dn;
            float4 v = __ldg(&h4[(size_t)s * 32 + lane]);
            acc.x = fmaf(v.x, w, acc.x);
            acc.y = fmaf(v.y, w, acc.y);
            acc.z = fmaf(v.z, w, acc.z);
            acc.w = fmaf(v.w, w, acc.w);
        }
    }
    if (RELU) {
        float4 b = *reinterpret_cast<const float4*>(bias + lane * 4);
        acc.x = fmaxf(acc.x + b.x, 0.0f);
        acc.y = fmaxf(acc.y + b.y, 0.0f);
        acc.z = fmaxf(acc.z + b.z, 0.0f);
        acc.w = fmaxf(acc.w + b.w, 0.0f);
    }
    reinterpret_cast<float4*>(agg)[(size_t)node * 32 + lane] = acc;
}

// ---------------- segment max (optional bias folded in) ----------------
__global__ void k_poolmax(const float* __restrict__ h, const float* __restrict__ bias,
                          float* __restrict__ out)
{
    int g = blockIdx.x, j = threadIdx.x;
    const float* p = h + (size_t)g * NPG * HH + j;
    float m = -INFINITY;
#pragma unroll 8
    for (int n = 0; n < NPG; n++) m = fmaxf(m, p[(size_t)n * HH]);
    if (bias) m += __ldg(&bias[j]);
    out[g * HH + j] = m;
}

// ---------------- root transform ----------------
__global__ void k_root(const float* __restrict__ x, const float* __restrict__ Wr,
                       const float* __restrict__ br, float* __restrict__ out)
{
    __shared__ float xs[FF];
    int g = blockIdx.x, j = threadIdx.x;
    const float* xr = x + (size_t)g * NPG * FF;
    for (int k = j; k < FF; k += HH) xs[k] = xr[k];
    __syncthreads();
    float acc = __ldg(&br[j]);
#pragma unroll 8
    for (int k = 0; k < FF; k++)
        acc = fmaf(xs[k], __ldg(&Wr[(size_t)k * HH + j]), acc);
    out[g * HH + j] = fmaxf(acc, 0.0f);
}

// ---------------- head (+ arange tail) ----------------
__global__ void k_head(const float* __restrict__ pool2, const float* __restrict__ Wl,
                       const float* __restrict__ bl, float* __restrict__ out, int extra)
{
    if (blockIdx.x >= BB / 8) {             // tail: idx = arange(B) as floats
        int t = (blockIdx.x - BB / 8) * 256 + threadIdx.x;
        if (t < extra) out[BB * CC + t] = (float)t;
        return;
    }
    int g = blockIdx.x * 8 + (threadIdx.x >> 5);
    int lane = threadIdx.x & 31;
    float a0 = 0.f, a1 = 0.f, a2 = 0.f, a3 = 0.f;
    for (int k = lane; k < 3 * HH; k += 32) {
        float v = (k < HH) ? g_root[g * HH + k]
                : (k < 2 * HH) ? pool2[g * HH + k - HH]
                : g_pool1[g * HH + k - 2 * HH];
        float4 w = __ldg(reinterpret_cast<const float4*>(Wl) + k);
        a0 = fmaf(v, w.x, a0); a1 = fmaf(v, w.y, a1);
        a2 = fmaf(v, w.z, a2); a3 = fmaf(v, w.w, a3);
    }
#pragma unroll
    for (int o = 16; o > 0; o >>= 1) {
        a0 += __shfl_xor_sync(0xffffffffu, a0, o);
        a1 += __shfl_xor_sync(0xffffffffu, a1, o);
        a2 += __shfl_xor_sync(0xffffffffu, a2, o);
        a3 += __shfl_xor_sync(0xffffffffu, a3, o);
    }
    if (lane == 0) {
        float l0 = a0 + __ldg(&bl[0]);
        float l1 = a1 + __ldg(&bl[1]);
        float l2 = a2 + __ldg(&bl[2]);
        float l3 = a3 + __ldg(&bl[3]);
        float m = fmaxf(fmaxf(l0, l1), fmaxf(l2, l3));
        float s = expf(l0 - m) + expf(l1 - m) + expf(l2 - m) + expf(l3 - m);
        float lse = m + logf(s);
        out[g * CC + 0] = l0 - lse;
        out[g * CC + 1] = l1 - lse;
        out[g * CC + 2] = l2 - lse;
        out[g * CC + 3] = l3 - lse;
    }
}

// ---------------- launch: forked-graph schedule ----------------
extern "C" void kernel_launch(void* const* d_in, const int* in_sizes, int n_in,
                              void* d_out, int out_size)
{
    const float* x  = (const float*)d_in[0];
    const int*   ei = (const int*)d_in[1];
    const float* W1 = (const float*)d_in[3];
    const float* b1 = (const float*)d_in[4];
    const float* W2 = (const float*)d_in[5];
    const float* b2 = (const float*)d_in[6];
    const float* Wr = (const float*)d_in[7];
    const float* br = (const float*)d_in[8];
    const float* Wl = (const float*)d_in[9];
    const float* bl = (const float*)d_in[10];
    float* out = (float*)d_out;

    float *h1pre, *t2pre, *agg1, *agg2, *pool1, *pool2, *root;
    cudaGetSymbolAddress((void**)&h1pre, g_h1pre);
    cudaGetSymbolAddress((void**)&t2pre, g_t2pre);
    cudaGetSymbolAddress((void**)&agg1,  g_agg1);
    cudaGetSymbolAddress((void**)&agg2,  g_agg2);
    cudaGetSymbolAddress((void**)&pool1, g_pool1);
    cudaGetSymbolAddress((void**)&pool2, g_pool2);
    cudaGetSymbolAddress((void**)&root,  g_root);

    cudaFuncSetAttribute(k_mma_x2, cudaFuncAttributeMaxDynamicSharedMemorySize, X_SMEM);
    cudaFuncSetAttribute(k_mma_h,  cudaFuncAttributeMaxDynamicSharedMemorySize, H_SMEM);

    // Side stream + events for a forked capture graph. Created per call and
    // intentionally leaked (host objects only; kernel_launch executes host code
    // only a handful of times — graph replays never re-run it). Destroying them
    // here could invalidate an ongoing capture, so we don't.
    cudaStream_t s2;
    cudaStreamCreateWithFlags(&s2, cudaStreamNonBlocking);
    cudaEvent_t evFork, evB, evP1, evC;
    cudaEventCreateWithFlags(&evFork, cudaEventDisableTiming);
    cudaEventCreateWithFlags(&evB,    cudaEventDisableTiming);
    cudaEventCreateWithFlags(&evP1,   cudaEventDisableTiming);
    cudaEventCreateWithFlags(&evC,    cudaEventDisableTiming);

    // fork
    cudaEventRecord(evFork, 0);
    cudaStreamWaitEvent(s2, evFork, 0);

    // Branch B (s2): weight prep -> big dual GEMM   (tensor-bound, ~120us)
    k_wprep<<<(HH * FF + 255) / 256, 256, 0, s2>>>(W1, W2);
    k_mma_x2<<<NN / 128, 256, X_SMEM, s2>>>(x);
    cudaEventRecord(evB, s2);

    // Branch A (stream 0): CSR build + root          (memory-bound, ~90us)
    k_zero_cnt<<<NN / 256, 256>>>();
    k_deg_count<<<(2 * EE) / 256, 256>>>(ei);
    k_scan1<<<512, 256>>>();
    k_scan2<<<1, 512>>>();
    k_scan3<<<512, 256>>>();
    k_fill<<<(2 * EE) / 256, 256>>>(ei);
    k_root<<<BB, HH>>>(x, Wr, br, root);

    // join: prop1 needs CSR (stream 0) + h1pre (evB)
    cudaStreamWaitEvent(0, evB, 0);
    k_prop_csr<true><<<NN / 8, 256>>>(h1pre, agg1, b1);
    cudaEventRecord(evP1, 0);

    // fork: pool1 on s2 runs concurrently with mma_h
    cudaStreamWaitEvent(s2, evP1, 0);
    k_poolmax<<<BB, HH, 0, s2>>>(agg1, nullptr, pool1);
    cudaEventRecord(evC, s2);

    // stream 0: t2pre += h1 @ W2b ; conv2 ; pool2
    k_mma_h<<<NN / 128, 256, H_SMEM>>>(agg1);
    k_prop_csr<false><<<NN / 8, 256>>>(t2pre, agg2, nullptr);
    k_poolmax<<<BB, HH>>>(agg2, b2, pool2);

    // join: head needs pool1 (evC) + pool2/root (stream 0)
    cudaStreamWaitEvent(0, evC, 0);
    int extra = out_size - BB * CC;
    int tailBlocks = (extra > 0) ? (extra + 255) / 256 : 0;
    k_head<<<BB / 8 + tailBlocks, 256>>>(pool2, Wl, bl, out, extra);
}

// round 14
// speedup vs baseline: 1.0986x; 1.0226x over previous
#include <cuda_runtime.h>
#include <cuda_fp16.h>
#include <math.h>
#include <stdint.h>

// ---------------- problem constants ----------------
#define NN 131072       // nodes
#define FF 768          // input features
#define HH 128          // hidden
#define BB 512          // graphs
#define NPG 256         // nodes per graph
#define EE 1048576      // directed edges (before symmetrization)
#define CC 4            // classes

// ---------------- scratch (device globals; no allocation) ----------------
__device__ float g_dinv[NN];
__device__ int   g_cnt[NN];
__device__ int   g_rowptr[NN + 1];
__device__ int   g_blksum[512];
__device__ int   g_cursor[NN];
__device__ int   g_esrc[2 * EE];

__device__ __align__(16) float g_h1pre[(size_t)NN * HH];   // X @ W1
__device__ __align__(16) float g_t2pre[(size_t)NN * HH];   // X @ W2a (+ h1 @ W2b)
__device__ __align__(16) float g_agg1[(size_t)NN * HH];    // conv1 out = h1 (relu'd)
__device__ int      g_pool1i[BB * HH];   // pool1 as int-compare floats (>=0)
__device__ unsigned g_pool2u[BB * HH];   // pool2 monotonic-encoded
__device__ float    g_root[BB * HH];

// fp16 transposed weights: [H=128 rows][K] row-major (K contiguous)
__device__ __align__(16) __half g_w1t[HH * FF];
__device__ __align__(16) __half g_w2at[HH * FF];
__device__ __align__(16) __half g_w2bt[HH * HH];

// ================= low-level helpers =================
__device__ __forceinline__ uint32_t smem_to_u32(const void* p) {
    uint32_t a;
    asm("{ .reg .u64 t; cvta.to.shared.u64 t, %1; cvt.u32.u64 %0, t; }"
        : "=r"(a) : "l"(p));
    return a;
}

__device__ __forceinline__ void cp16(uint32_t sdst, const void* gsrc) {
    asm volatile("cp.async.cg.shared.global [%0], [%1], 16;"
                 :: "r"(sdst), "l"(gsrc));
}
#define CP_COMMIT() asm volatile("cp.async.commit_group;" ::: "memory")
#define CP_WAIT0()  asm volatile("cp.async.wait_group 0;" ::: "memory")

__device__ __forceinline__ void ldmx4(uint32_t* r, uint32_t addr) {
    asm volatile("ldmatrix.sync.aligned.m8n8.x4.shared.b16 {%0,%1,%2,%3}, [%4];"
        : "=r"(r[0]), "=r"(r[1]), "=r"(r[2]), "=r"(r[3]) : "r"(addr));
}

__device__ __forceinline__ void mma16816(float* c, const uint32_t* a, const uint32_t* b) {
    asm volatile(
        "mma.sync.aligned.m16n8k16.row.col.f32.f16.f16.f32 "
        "{%0,%1,%2,%3}, {%4,%5,%6,%7}, {%8,%9}, {%0,%1,%2,%3};"
        : "+f"(c[0]), "+f"(c[1]), "+f"(c[2]), "+f"(c[3])
        : "r"(a[0]), "r"(a[1]), "r"(a[2]), "r"(a[3]), "r"(b[0]), "r"(b[1]));
}

__device__ __forceinline__ uint32_t pack_h2(__half a, __half b) {
    __half2 t; t.x = a; t.y = b;
    return *reinterpret_cast<uint32_t*>(&t);
}

// monotonic float<->unsigned encoding (order-preserving for all floats)
__device__ __forceinline__ unsigned enc_f(float f) {
    unsigned b = __float_as_uint(f);
    return (b & 0x80000000u) ? ~b : (b | 0x80000000u);
}
__device__ __forceinline__ float dec_f(unsigned u) {
    unsigned b = (u & 0x80000000u) ? (u & 0x7FFFFFFFu) : ~u;
    return __uint_as_float(b);
}

// fp16 tile smem layout: 4 k16-blocks of [128 rows][32B]; stride 4128 + XOR swizzle.
#define BLKS  4128
#define TILE  16512          // one [128 x 64] fp16 tile (4 * BLKS)
__device__ __forceinline__ int swoff(int kb, int m, int c) {
    return kb * BLKS + m * 32 + ((c ^ ((m >> 2) & 1)) << 4);
}

// pipelined GEMM smem maps (single-pass fp16)
#define AR_OFF   0                         // raw fp32 A tile [128 x 64], 32768 B
#define ABF_OFF  32768                     // fp16 A tile (TILE bytes)
#define BB0_OFF  (ABF_OFF + TILE)          // 49280
#define X_SMEM   (BB0_OFF + 2 * 2 * TILE)  // 115328 (2 B tiles, double buffered)
#define H_SMEM   (BB0_OFF + 2 * 1 * TILE)  // 82304  (1 B tile,  double buffered)

// ---- cp.async: raw fp32 A tile -> AR staging ----
__device__ __forceinline__ void cpA(uint32_t sb, const float* __restrict__ A,
                                    int Ktot, int rowBase, int kc, int tid)
{
#pragma unroll
    for (int i = 0; i < 8; i++) {
        int f = i * 256 + tid;             // 2048 x 16B chunks
        int row = f >> 4, c = f & 15;
        cp16(sb + AR_OFF + row * 256 + c * 16,
             A + (size_t)(rowBase + row) * Ktot + kc * 64 + c * 4);
    }
}

// ---- convert AR (fp32) -> ABF (fp16, swizzled) ----
__device__ __forceinline__ void convert_AR(char* sm, int tid) {
#pragma unroll
    for (int i = 0; i < 8; i++) {
        int f = i * 256 + tid;
        int row = f >> 4, c = f & 15;
        float4 v = *reinterpret_cast<const float4*>(sm + AR_OFF + row * 256 + c * 16);
        int off = swoff(c >> 2, row, (c >> 1) & 1) + (c & 1) * 8;
        *reinterpret_cast<uint2*>(sm + ABF_OFF + off) =
            make_uint2(pack_h2(__float2half_rn(v.x), __float2half_rn(v.y)),
                       pack_h2(__float2half_rn(v.z), __float2half_rn(v.w)));
    }
}

// ---- fragment loaders ----
__device__ __forceinline__ void load_a_frags1(uint32_t abase, int ks, int wM, int lane,
                                              uint32_t ah[4][4])
{
#pragma unroll
    for (int mt = 0; mt < 4; mt++) {
        int r = wM + mt * 16 + (lane & 15);
        int c = lane >> 4;
        ldmx4(ah[mt], abase + (uint32_t)swoff(ks, r, c));
    }
}

__device__ __forceinline__ void load_b_frags(uint32_t bbase, int ks, int wN, int lane,
                                             uint32_t bf[4][2])
{
#pragma unroll
    for (int nt2 = 0; nt2 < 2; nt2++) {
        int n = wN + nt2 * 16 + (lane & 7) + ((lane >> 4) << 3);
        int c = (lane >> 3) & 1;
        uint32_t t[4];
        ldmx4(t, bbase + (uint32_t)swoff(ks, n, c));
        bf[nt2 * 2][0] = t[0]; bf[nt2 * 2][1] = t[1];
        bf[nt2 * 2 + 1][0] = t[2]; bf[nt2 * 2 + 1][1] = t[3];
    }
}

// ======= pipelined dual-output GEMM: h1pre = X@W1^T, t2pre = X@W2a^T =======
__global__ void __launch_bounds__(256, 1) k_mma_x2(const float* __restrict__ X) {
    extern __shared__ char sm[];
    const uint32_t sb = smem_to_u32(sm);
    const int tid = threadIdx.x;
    const int lane = tid & 31;
    const int wid = tid >> 5;
    const int wM = (wid & 1) * 64;
    const int wN = (wid >> 1) * 32;
    const int rowBase = blockIdx.x * 128;

    float acc1[4][4][4], acc2[4][4][4];
#pragma unroll
    for (int i = 0; i < 4; i++)
#pragma unroll
        for (int j = 0; j < 4; j++)
#pragma unroll
            for (int q = 0; q < 4; q++) { acc1[i][j][q] = 0.0f; acc2[i][j][q] = 0.0f; }

    cpA(sb, X, FF, rowBase, 0, tid);
#pragma unroll
    for (int it = 0; it < 4; it++) {
        int u = it * 256 + tid;
        int n = u >> 3, ch = u & 7;
        size_t go = (size_t)n * FF + ch * 8;
        int off = swoff(ch >> 1, n, ch & 1);
        cp16(sb + BB0_OFF + off,        g_w1t + go);
        cp16(sb + BB0_OFF + TILE + off, g_w2at + go);
    }
    CP_COMMIT();

    for (int kc = 0; kc < FF / 64; kc++) {
        CP_WAIT0();
        __syncthreads();
        convert_AR(sm, tid);
        __syncthreads();

        if (kc + 1 < FF / 64) {
            cpA(sb, X, FF, rowBase, kc + 1, tid);
            uint32_t bdst = sb + BB0_OFF + (uint32_t)(((kc + 1) & 1) * 2 * TILE);
#pragma unroll
            for (int it = 0; it < 4; it++) {
                int u = it * 256 + tid;
                int n = u >> 3, ch = u & 7;
                size_t go = (size_t)n * FF + (kc + 1) * 64 + ch * 8;
                int off = swoff(ch >> 1, n, ch & 1);
                cp16(bdst + off,        g_w1t + go);
                cp16(bdst + TILE + off, g_w2at + go);
            }
            CP_COMMIT();
        }

        uint32_t bbB = sb + BB0_OFF + (uint32_t)((kc & 1) * 2 * TILE);
#pragma unroll
        for (int ks = 0; ks < 4; ks++) {
            uint32_t ah[4][4];
            load_a_frags1(sb + ABF_OFF, ks, wM, lane, ah);
            {
                uint32_t bh[4][2];
                load_b_frags(bbB, ks, wN, lane, bh);
#pragma unroll
                for (int mt = 0; mt < 4; mt++)
#pragma unroll
                    for (int nt = 0; nt < 4; nt++)
                        mma16816(acc1[mt][nt], ah[mt], bh[nt]);
            }
            {
                uint32_t bh[4][2];
                load_b_frags(bbB + TILE, ks, wN, lane, bh);
#pragma unroll
                for (int mt = 0; mt < 4; mt++)
#pragma unroll
                    for (int nt = 0; nt < 4; nt++)
                        mma16816(acc2[mt][nt], ah[mt], bh[nt]);
            }
        }
    }

#pragma unroll
    for (int mt = 0; mt < 4; mt++) {
        int row = rowBase + wM + mt * 16 + (lane >> 2);
#pragma unroll
        for (int nt = 0; nt < 4; nt++) {
            int col = wN + nt * 8 + (lane & 3) * 2;
            *reinterpret_cast<float2*>(&g_h1pre[(size_t)row * HH + col]) =
                make_float2(acc1[mt][nt][0], acc1[mt][nt][1]);
            *reinterpret_cast<float2*>(&g_h1pre[(size_t)(row + 8) * HH + col]) =
                make_float2(acc1[mt][nt][2], acc1[mt][nt][3]);
            *reinterpret_cast<float2*>(&g_t2pre[(size_t)row * HH + col]) =
                make_float2(acc2[mt][nt][0], acc2[mt][nt][1]);
            *reinterpret_cast<float2*>(&g_t2pre[(size_t)(row + 8) * HH + col]) =
                make_float2(acc2[mt][nt][2], acc2[mt][nt][3]);
        }
    }
}

// ======= pipelined accumulating GEMM: t2pre += h1 @ W2b^T (K = 128) =======
__global__ void __launch_bounds__(256, 1) k_mma_h(const float* __restrict__ A) {
    extern __shared__ char sm[];
    const uint32_t sb = smem_to_u32(sm);
    const int tid = threadIdx.x;
    const int lane = tid & 31;
    const int wid = tid >> 5;
    const int wM = (wid & 1) * 64;
    const int wN = (wid >> 1) * 32;
    const int rowBase = blockIdx.x * 128;

    float acc[4][4][4];
#pragma unroll
    for (int i = 0; i < 4; i++)
#pragma unroll
        for (int j = 0; j < 4; j++)
#pragma unroll
            for (int q = 0; q < 4; q++) acc[i][j][q] = 0.0f;

    cpA(sb, A, HH, rowBase, 0, tid);
#pragma unroll
    for (int it = 0; it < 4; it++) {
        int u = it * 256 + tid;
        int n = u >> 3, ch = u & 7;
        size_t go = (size_t)n * HH + ch * 8;
        int off = swoff(ch >> 1, n, ch & 1);
        cp16(sb + BB0_OFF + off, g_w2bt + go);
    }
    CP_COMMIT();

    for (int kc = 0; kc < 2; kc++) {
        CP_WAIT0();
        __syncthreads();
        convert_AR(sm, tid);
        __syncthreads();

        if (kc == 0) {
            cpA(sb, A, HH, rowBase, 1, tid);
            uint32_t bdst = sb + BB0_OFF + TILE;
#pragma unroll
            for (int it = 0; it < 4; it++) {
                int u = it * 256 + tid;
                int n = u >> 3, ch = u & 7;
                size_t go = (size_t)n * HH + 64 + ch * 8;
                int off = swoff(ch >> 1, n, ch & 1);
                cp16(bdst + off, g_w2bt + go);
            }
            CP_COMMIT();
        }

        uint32_t bbB = sb + BB0_OFF + (uint32_t)(kc * TILE);
#pragma unroll
        for (int ks = 0; ks < 4; ks++) {
            uint32_t ah[4][4];
            load_a_frags1(sb + ABF_OFF, ks, wM, lane, ah);
            uint32_t bh[4][2];
            load_b_frags(bbB, ks, wN, lane, bh);
#pragma unroll
            for (int mt = 0; mt < 4; mt++)
#pragma unroll
                for (int nt = 0; nt < 4; nt++)
                    mma16816(acc[mt][nt], ah[mt], bh[nt]);
        }
    }

#pragma unroll
    for (int mt = 0; mt < 4; mt++) {
        int row = rowBase + wM + mt * 16 + (lane >> 2);
#pragma unroll
        for (int nt = 0; nt < 4; nt++) {
            int col = wN + nt * 8 + (lane & 3) * 2;
            float2* p0 = reinterpret_cast<float2*>(&g_t2pre[(size_t)row * HH + col]);
            float2* p1 = reinterpret_cast<float2*>(&g_t2pre[(size_t)(row + 8) * HH + col]);
            float2 e0 = *p0, e1 = *p1;
            *p0 = make_float2(acc[mt][nt][0] + e0.x, acc[mt][nt][1] + e0.y);
            *p1 = make_float2(acc[mt][nt][2] + e1.x, acc[mt][nt][3] + e1.y);
        }
    }
}

// ---------------- weight prep: transpose to fp16 ----------------
__global__ void k_wprep(const float* __restrict__ W1, const float* __restrict__ W2) {
    int t = blockIdx.x * blockDim.x + threadIdx.x;
    if (t >= HH * FF) return;
    int h = t / FF, k = t % FF;
    g_w1t[t]  = __float2half_rn(W1[(size_t)k * HH + h]);
    g_w2at[t] = __float2half_rn(W2[(size_t)k * HH + h]);
    if (t < HH * HH) {
        int h2 = t / HH, k2 = t % HH;
        g_w2bt[t] = __float2half_rn(W2[(size_t)(FF + k2) * HH + h2]);
    }
}

// ---------------- degree / CSR build ----------------
// zero counters + init fused pool buffers
__global__ void k_zero_cnt() {
    int i = blockIdx.x * blockDim.x + threadIdx.x;
    if (i < NN) g_cnt[i] = 0;
    if (i < BB * HH) { g_pool1i[i] = 0; g_pool2u[i] = 0u; }
}

__global__ void k_deg_count(const int* __restrict__ ei) {
    int t = blockIdx.x * blockDim.x + threadIdx.x;
    if (t < 2 * EE) atomicAdd(&g_cnt[__ldg(&ei[t])], 1);
}

// scan1 with fused deg_fin (dinv + cursor init)
__global__ void k_scan1() {
    __shared__ int sh[256];
    int tid = threadIdx.x;
    int i = blockIdx.x * 256 + tid;
    int v = g_cnt[i];
    g_dinv[i] = rsqrtf((float)v + 1.0f);   // +1 self loop
    g_cursor[i] = 0;
    sh[tid] = v;
    __syncthreads();
#pragma unroll
    for (int o = 1; o < 256; o <<= 1) {
        int t = (tid >= o) ? sh[tid - o] : 0;
        __syncthreads();
        sh[tid] += t;
        __syncthreads();
    }
    g_rowptr[i] = sh[tid] - v;
    if (tid == 255) g_blksum[blockIdx.x] = sh[255];
}

__global__ void k_scan2() {
    __shared__ int sh[512];
    int tid = threadIdx.x;
    int v = g_blksum[tid];
    sh[tid] = v;
    __syncthreads();
#pragma unroll
    for (int o = 1; o < 512; o <<= 1) {
        int t = (tid >= o) ? sh[tid - o] : 0;
        __syncthreads();
        sh[tid] += t;
        __syncthreads();
    }
    g_blksum[tid] = sh[tid] - v;
}

__global__ void k_scan3() {
    int i = blockIdx.x * 256 + threadIdx.x;
    g_rowptr[i] += g_blksum[blockIdx.x];
    if (i == NN - 1) g_rowptr[NN] = 2 * EE;
}

__global__ void k_fill(const int* __restrict__ ei) {
    int t = blockIdx.x * blockDim.x + threadIdx.x;
    if (t >= 2 * EE) return;
    int src = __ldg(&ei[t]);
    int dst = (t < EE) ? __ldg(&ei[t + EE]) : __ldg(&ei[t - EE]);
    int pos = g_rowptr[dst] + atomicAdd(&g_cursor[dst], 1);
    g_esrc[pos] = src;
}

// ---------------- common gather body ----------------
__device__ __forceinline__ float4 prop_gather(const float* __restrict__ h,
                                              int node, int lane)
{
    const float4* h4 = reinterpret_cast<const float4*>(h);
    float dn = __ldg(&g_dinv[node]);
    float4 acc = __ldg(&h4[(size_t)node * 32 + lane]);
    float s2 = dn * dn;
    acc.x *= s2; acc.y *= s2; acc.z *= s2; acc.w *= s2;
    int start = __ldg(&g_rowptr[node]);
    int end   = __ldg(&g_rowptr[node + 1]);
    for (int base = start; base < end; base += 32) {
        int n = min(32, end - base);
        int si = (base + lane < end) ? __ldg(&g_esrc[base + lane]) : 0;
#pragma unroll 4
        for (int j = 0; j < n; j++) {
            int s = __shfl_sync(0xffffffffu, si, j);
            float w = __ldg(&g_dinv[s]) * dn;
            float4 v = __ldg(&h4[(size_t)s * 32 + lane]);
            acc.x = fmaf(v.x, w, acc.x);
            acc.y = fmaf(v.y, w, acc.y);
            acc.z = fmaf(v.z, w, acc.z);
            acc.w = fmaf(v.w, w, acc.w);
        }
    }
    return acc;
}

// conv1: agg1 = relu(prop + b1); pool1 fused (block max -> global atomicMax).
// 8 consecutive nodes per block => all in the same graph (NPG=256, blocks 8-aligned).
__global__ void __launch_bounds__(256) k_prop1(const float* __restrict__ h,
                                               float* __restrict__ agg,
                                               const float* __restrict__ bias)
{
    __shared__ int pmax[HH];
    int node = blockIdx.x * 8 + (threadIdx.x >> 5);
    int lane = threadIdx.x & 31;
    if (threadIdx.x < HH) pmax[threadIdx.x] = 0;   // relu => values >= 0
    __syncthreads();

    float4 acc = prop_gather(h, node, lane);
    float4 b = *reinterpret_cast<const float4*>(bias + lane * 4);
    acc.x = fmaxf(acc.x + b.x, 0.0f);
    acc.y = fmaxf(acc.y + b.y, 0.0f);
    acc.z = fmaxf(acc.z + b.z, 0.0f);
    acc.w = fmaxf(acc.w + b.w, 0.0f);
    reinterpret_cast<float4*>(agg)[(size_t)node * 32 + lane] = acc;

    // non-negative floats: int compare == float compare
    atomicMax(&pmax[lane * 4 + 0], __float_as_int(acc.x));
    atomicMax(&pmax[lane * 4 + 1], __float_as_int(acc.y));
    atomicMax(&pmax[lane * 4 + 2], __float_as_int(acc.z));
    atomicMax(&pmax[lane * 4 + 3], __float_as_int(acc.w));
    __syncthreads();
    if (threadIdx.x < HH) {
        int g = (blockIdx.x * 8) >> 8;
        atomicMax(&g_pool1i[g * HH + threadIdx.x], pmax[threadIdx.x]);
    }
}

// conv2: pool2 fused; agg2 never materialized (pool2 was its only consumer).
__global__ void __launch_bounds__(256) k_prop2(const float* __restrict__ h)
{
    __shared__ unsigned pmax[HH];
    int node = blockIdx.x * 8 + (threadIdx.x >> 5);
    int lane = threadIdx.x & 31;
    if (threadIdx.x < HH) pmax[threadIdx.x] = 0u;  // below enc of any float
    __syncthreads();

    float4 acc = prop_gather(h, node, lane);
    atomicMax(&pmax[lane * 4 + 0], enc_f(acc.x));
    atomicMax(&pmax[lane * 4 + 1], enc_f(acc.y));
    atomicMax(&pmax[lane * 4 + 2], enc_f(acc.z));
    atomicMax(&pmax[lane * 4 + 3], enc_f(acc.w));
    __syncthreads();
    if (threadIdx.x < HH) {
        int g = (blockIdx.x * 8) >> 8;
        atomicMax(&g_pool2u[g * HH + threadIdx.x], pmax[threadIdx.x]);
    }
}

// ---------------- root transform ----------------
__global__ void k_root(const float* __restrict__ x, const float* __restrict__ Wr,
                       const float* __restrict__ br, float* __restrict__ out)
{
    __shared__ float xs[FF];
    int g = blockIdx.x, j = threadIdx.x;
    const float* xr = x + (size_t)g * NPG * FF;
    for (int k = j; k < FF; k += HH) xs[k] = xr[k];
    __syncthreads();
    float acc = __ldg(&br[j]);
#pragma unroll 8
    for (int k = 0; k < FF; k++)
        acc = fmaf(xs[k], __ldg(&Wr[(size_t)k * HH + j]), acc);
    out[g * HH + j] = fmaxf(acc, 0.0f);
}

// ---------------- head (+ arange tail) ----------------
__global__ void k_head(const float* __restrict__ b2, const float* __restrict__ Wl,
                       const float* __restrict__ bl, float* __restrict__ out, int extra)
{
    if (blockIdx.x >= BB / 8) {             // tail: idx = arange(B) as floats
        int t = (blockIdx.x - BB / 8) * 256 + threadIdx.x;
        if (t < extra) out[BB * CC + t] = (float)t;
        return;
    }
    int g = blockIdx.x * 8 + (threadIdx.x >> 5);
    int lane = threadIdx.x & 31;
    float a0 = 0.f, a1 = 0.f, a2 = 0.f, a3 = 0.f;
    for (int k = lane; k < 3 * HH; k += 32) {
        float v;
        if (k < HH)            v = g_root[g * HH + k];
        else if (k < 2 * HH)   v = dec_f(g_pool2u[g * HH + k - HH]) + __ldg(&b2[k - HH]);
        else                   v = __int_as_float(g_pool1i[g * HH + k - 2 * HH]);
        float4 w = __ldg(reinterpret_cast<const float4*>(Wl) + k);
        a0 = fmaf(v, w.x, a0); a1 = fmaf(v, w.y, a1);
        a2 = fmaf(v, w.z, a2); a3 = fmaf(v, w.w, a3);
    }
#pragma unroll
    for (int o = 16; o > 0; o >>= 1) {
        a0 += __shfl_xor_sync(0xffffffffu, a0, o);
        a1 += __shfl_xor_sync(0xffffffffu, a1, o);
        a2 += __shfl_xor_sync(0xffffffffu, a2, o);
        a3 += __shfl_xor_sync(0xffffffffu, a3, o);
    }
    if (lane == 0) {
        float l0 = a0 + __ldg(&bl[0]);
        float l1 = a1 + __ldg(&bl[1]);
        float l2 = a2 + __ldg(&bl[2]);
        float l3 = a3 + __ldg(&bl[3]);
        float m = fmaxf(fmaxf(l0, l1), fmaxf(l2, l3));
        float s = expf(l0 - m) + expf(l1 - m) + expf(l2 - m) + expf(l3 - m);
        float lse = m + logf(s);
        out[g * CC + 0] = l0 - lse;
        out[g * CC + 1] = l1 - lse;
        out[g * CC + 2] = l2 - lse;
        out[g * CC + 3] = l3 - lse;
    }
}

// ---------------- launch: forked-graph schedule ----------------
extern "C" void kernel_launch(void* const* d_in, const int* in_sizes, int n_in,
                              void* d_out, int out_size)
{
    const float* x  = (const float*)d_in[0];
    const int*   ei = (const int*)d_in[1];
    const float* W1 = (const float*)d_in[3];
    const float* b1 = (const float*)d_in[4];
    const float* W2 = (const float*)d_in[5];
    const float* b2 = (const float*)d_in[6];
    const float* Wr = (const float*)d_in[7];
    const float* br = (const float*)d_in[8];
    const float* Wl = (const float*)d_in[9];
    const float* bl = (const float*)d_in[10];
    float* out = (float*)d_out;

    float *h1pre, *t2pre, *agg1, *root;
    cudaGetSymbolAddress((void**)&h1pre, g_h1pre);
    cudaGetSymbolAddress((void**)&t2pre, g_t2pre);
    cudaGetSymbolAddress((void**)&agg1,  g_agg1);
    cudaGetSymbolAddress((void**)&root,  g_root);

    cudaFuncSetAttribute(k_mma_x2, cudaFuncAttributeMaxDynamicSharedMemorySize, X_SMEM);
    cudaFuncSetAttribute(k_mma_h,  cudaFuncAttributeMaxDynamicSharedMemorySize, H_SMEM);

    // Side stream + events for the forked capture graph (host objects leaked
    // deliberately; replays never re-run host code).
    cudaStream_t s2;
    cudaStreamCreateWithFlags(&s2, cudaStreamNonBlocking);
    cudaEvent_t evFork, evB;
    cudaEventCreateWithFlags(&evFork, cudaEventDisableTiming);
    cudaEventCreateWithFlags(&evB,    cudaEventDisableTiming);

    // fork
    cudaEventRecord(evFork, 0);
    cudaStreamWaitEvent(s2, evFork, 0);

    // Branch B (s2): weight prep -> big dual GEMM  (tensor-bound)
    k_wprep<<<(HH * FF + 255) / 256, 256, 0, s2>>>(W1, W2);
    k_mma_x2<<<NN / 128, 256, X_SMEM, s2>>>(x);
    cudaEventRecord(evB, s2);

    // Branch A (stream 0): CSR build + root + pool init  (memory-bound)
    k_zero_cnt<<<NN / 256, 256>>>();
    k_deg_count<<<(2 * EE) / 256, 256>>>(ei);
    k_scan1<<<512, 256>>>();
    k_scan2<<<1, 512>>>();
    k_scan3<<<512, 256>>>();
    k_fill<<<(2 * EE) / 256, 256>>>(ei);
    k_root<<<BB, HH>>>(x, Wr, br, root);

    // join: prop1 needs CSR (stream 0) + h1pre (evB)
    cudaStreamWaitEvent(0, evB, 0);

    // conv1 propagate + bias/relu + fused pool1
    k_prop1<<<NN / 8, 256>>>(h1pre, agg1, b1);

    // t2pre += h1 @ W2b
    k_mma_h<<<NN / 128, 256, H_SMEM>>>(agg1);

    // conv2 propagate + fused pool2 (agg2 never materialized)
    k_prop2<<<NN / 8, 256>>>(t2pre);

    // head + tail
    int extra = out_size - BB * CC;
    int tailBlocks = (extra > 0) ? (extra + 255) / 256 : 0;
    k_head<<<BB / 8 + tailBlocks, 256>>>(b2, Wl, bl, out, extra);
}

// round 16
// speedup vs baseline: 1.1433x; 1.0407x over previous
#include <cuda_runtime.h>
#include <cuda_fp16.h>
#include <math.h>
#include <stdint.h>

// ---------------- problem constants ----------------
#define NN 131072       // nodes
#define FF 768          // input features
#define HH 128          // hidden
#define BB 512          // graphs
#define NPG 256         // nodes per graph
#define EE 1048576      // directed edges (before symmetrization)
#define CC 4            // classes

// ---------------- scratch (device globals; no allocation) ----------------
__device__ float g_dinv[NN];
__device__ int   g_cnt[NN];
__device__ int   g_rowptr[NN + 1];
__device__ int   g_blksum[512];
__device__ int   g_cursor[NN];
__device__ int   g_esrc[2 * EE];

__device__ __align__(16) float g_h1pre[(size_t)NN * HH];   // X @ W1
__device__ __align__(16) float g_t2pre[(size_t)NN * HH];   // X @ W2a; mma_h rewrites *dinv
__device__ __align__(16) float g_agg1[(size_t)NN * HH];    // conv1 out = h1 (relu'd)
__device__ int      g_pool1i[BB * HH];   // pool1 as int-compare floats (>=0)
__device__ unsigned g_pool2u[BB * HH];   // pool2 monotonic-encoded
__device__ float    g_root[BB * HH];

// fp16 transposed weights: [H=128 rows][K] row-major (K contiguous)
__device__ __align__(16) __half g_w1t[HH * FF];
__device__ __align__(16) __half g_w2at[HH * FF];
__device__ __align__(16) __half g_w2bt[HH * HH];

// ================= low-level helpers =================
__device__ __forceinline__ uint32_t smem_to_u32(const void* p) {
    uint32_t a;
    asm("{ .reg .u64 t; cvta.to.shared.u64 t, %1; cvt.u32.u64 %0, t; }"
        : "=r"(a) : "l"(p));
    return a;
}

__device__ __forceinline__ void cp16(uint32_t sdst, const void* gsrc) {
    asm volatile("cp.async.cg.shared.global [%0], [%1], 16;"
                 :: "r"(sdst), "l"(gsrc));
}
#define CP_COMMIT() asm volatile("cp.async.commit_group;" ::: "memory")
#define CP_WAIT0()  asm volatile("cp.async.wait_group 0;" ::: "memory")

__device__ __forceinline__ void ldmx4(uint32_t* r, uint32_t addr) {
    asm volatile("ldmatrix.sync.aligned.m8n8.x4.shared.b16 {%0,%1,%2,%3}, [%4];"
        : "=r"(r[0]), "=r"(r[1]), "=r"(r[2]), "=r"(r[3]) : "r"(addr));
}

__device__ __forceinline__ void mma16816(float* c, const uint32_t* a, const uint32_t* b) {
    asm volatile(
        "mma.sync.aligned.m16n8k16.row.col.f32.f16.f16.f32 "
        "{%0,%1,%2,%3}, {%4,%5,%6,%7}, {%8,%9}, {%0,%1,%2,%3};"
        : "+f"(c[0]), "+f"(c[1]), "+f"(c[2]), "+f"(c[3])
        : "r"(a[0]), "r"(a[1]), "r"(a[2]), "r"(a[3]), "r"(b[0]), "r"(b[1]));
}

__device__ __forceinline__ uint32_t pack_h2(__half a, __half b) {
    __half2 t; t.x = a; t.y = b;
    return *reinterpret_cast<uint32_t*>(&t);
}

// monotonic float<->unsigned encoding (order-preserving)
__device__ __forceinline__ unsigned enc_f(float f) {
    unsigned b = __float_as_uint(f);
    return (b & 0x80000000u) ? ~b : (b | 0x80000000u);
}
__device__ __forceinline__ float dec_f(unsigned u) {
    unsigned b = (u & 0x80000000u) ? (u & 0x7FFFFFFFu) : ~u;
    return __uint_as_float(b);
}

// fp16 tile smem layout: 4 k16-blocks of [128 rows][32B]; stride 4128 + XOR swizzle.
#define BLKS  4128
#define TILE  16512          // one [128 x 64] fp16 tile (4 * BLKS)
__device__ __forceinline__ int swoff(int kb, int m, int c) {
    return kb * BLKS + m * 32 + ((c ^ ((m >> 2) & 1)) << 4);
}

// pipelined GEMM smem maps (single-pass fp16)
#define AR_OFF   0                         // raw fp32 A tile [128 x 64], 32768 B
#define ABF_OFF  32768                     // fp16 A tile (TILE bytes)
#define BB0_OFF  (ABF_OFF + TILE)          // 49280
#define X_SMEM   (BB0_OFF + 2 * 2 * TILE)  // 115328 (2 B tiles, double buffered)
#define H_SMEM   (BB0_OFF + 2 * 1 * TILE)  // 82304  (1 B tile,  double buffered)

// ---- cp.async: raw fp32 A tile -> AR staging ----
__device__ __forceinline__ void cpA(uint32_t sb, const float* __restrict__ A,
                                    int Ktot, int rowBase, int kc, int tid)
{
#pragma unroll
    for (int i = 0; i < 8; i++) {
        int f = i * 256 + tid;             // 2048 x 16B chunks
        int row = f >> 4, c = f & 15;
        cp16(sb + AR_OFF + row * 256 + c * 16,
             A + (size_t)(rowBase + row) * Ktot + kc * 64 + c * 4);
    }
}

// ---- convert AR (fp32) -> ABF (fp16, swizzled) ----
__device__ __forceinline__ void convert_AR(char* sm, int tid) {
#pragma unroll
    for (int i = 0; i < 8; i++) {
        int f = i * 256 + tid;
        int row = f >> 4, c = f & 15;
        float4 v = *reinterpret_cast<const float4*>(sm + AR_OFF + row * 256 + c * 16);
        int off = swoff(c >> 2, row, (c >> 1) & 1) + (c & 1) * 8;
        *reinterpret_cast<uint2*>(sm + ABF_OFF + off) =
            make_uint2(pack_h2(__float2half_rn(v.x), __float2half_rn(v.y)),
                       pack_h2(__float2half_rn(v.z), __float2half_rn(v.w)));
    }
}

// ---- fragment loaders ----
__device__ __forceinline__ void load_a_frags1(uint32_t abase, int ks, int wM, int lane,
                                              uint32_t ah[4][4])
{
#pragma unroll
    for (int mt = 0; mt < 4; mt++) {
        int r = wM + mt * 16 + (lane & 15);
        int c = lane >> 4;
        ldmx4(ah[mt], abase + (uint32_t)swoff(ks, r, c));
    }
}

__device__ __forceinline__ void load_b_frags(uint32_t bbase, int ks, int wN, int lane,
                                             uint32_t bf[4][2])
{
#pragma unroll
    for (int nt2 = 0; nt2 < 2; nt2++) {
        int n = wN + nt2 * 16 + (lane & 7) + ((lane >> 4) << 3);
        int c = (lane >> 3) & 1;
        uint32_t t[4];
        ldmx4(t, bbase + (uint32_t)swoff(ks, n, c));
        bf[nt2 * 2][0] = t[0]; bf[nt2 * 2][1] = t[1];
        bf[nt2 * 2 + 1][0] = t[2]; bf[nt2 * 2 + 1][1] = t[3];
    }
}

// ======= pipelined dual-output GEMM: h1pre = X@W1^T, t2pre = X@W2a^T =======
__global__ void __launch_bounds__(256, 1) k_mma_x2(const float* __restrict__ X) {
    extern __shared__ char sm[];
    const uint32_t sb = smem_to_u32(sm);
    const int tid = threadIdx.x;
    const int lane = tid & 31;
    const int wid = tid >> 5;
    const int wM = (wid & 1) * 64;
    const int wN = (wid >> 1) * 32;
    const int rowBase = blockIdx.x * 128;

    float acc1[4][4][4], acc2[4][4][4];
#pragma unroll
    for (int i = 0; i < 4; i++)
#pragma unroll
        for (int j = 0; j < 4; j++)
#pragma unroll
            for (int q = 0; q < 4; q++) { acc1[i][j][q] = 0.0f; acc2[i][j][q] = 0.0f; }

    cpA(sb, X, FF, rowBase, 0, tid);
#pragma unroll
    for (int it = 0; it < 4; it++) {
        int u = it * 256 + tid;
        int n = u >> 3, ch = u & 7;
        size_t go = (size_t)n * FF + ch * 8;
        int off = swoff(ch >> 1, n, ch & 1);
        cp16(sb + BB0_OFF + off,        g_w1t + go);
        cp16(sb + BB0_OFF + TILE + off, g_w2at + go);
    }
    CP_COMMIT();

    for (int kc = 0; kc < FF / 64; kc++) {
        CP_WAIT0();
        __syncthreads();
        convert_AR(sm, tid);
        __syncthreads();

        if (kc + 1 < FF / 64) {
            cpA(sb, X, FF, rowBase, kc + 1, tid);
            uint32_t bdst = sb + BB0_OFF + (uint32_t)(((kc + 1) & 1) * 2 * TILE);
#pragma unroll
            for (int it = 0; it < 4; it++) {
                int u = it * 256 + tid;
                int n = u >> 3, ch = u & 7;
                size_t go = (size_t)n * FF + (kc + 1) * 64 + ch * 8;
                int off = swoff(ch >> 1, n, ch & 1);
                cp16(bdst + off,        g_w1t + go);
                cp16(bdst + TILE + off, g_w2at + go);
            }
            CP_COMMIT();
        }

        uint32_t bbB = sb + BB0_OFF + (uint32_t)((kc & 1) * 2 * TILE);
#pragma unroll
        for (int ks = 0; ks < 4; ks++) {
            uint32_t ah[4][4];
            load_a_frags1(sb + ABF_OFF, ks, wM, lane, ah);
            {
                uint32_t bh[4][2];
                load_b_frags(bbB, ks, wN, lane, bh);
#pragma unroll
                for (int mt = 0; mt < 4; mt++)
#pragma unroll
                    for (int nt = 0; nt < 4; nt++)
                        mma16816(acc1[mt][nt], ah[mt], bh[nt]);
            }
            {
                uint32_t bh[4][2];
                load_b_frags(bbB + TILE, ks, wN, lane, bh);
#pragma unroll
                for (int mt = 0; mt < 4; mt++)
#pragma unroll
                    for (int nt = 0; nt < 4; nt++)
                        mma16816(acc2[mt][nt], ah[mt], bh[nt]);
            }
        }
    }

#pragma unroll
    for (int mt = 0; mt < 4; mt++) {
        int row = rowBase + wM + mt * 16 + (lane >> 2);
#pragma unroll
        for (int nt = 0; nt < 4; nt++) {
            int col = wN + nt * 8 + (lane & 3) * 2;
            *reinterpret_cast<float2*>(&g_h1pre[(size_t)row * HH + col]) =
                make_float2(acc1[mt][nt][0], acc1[mt][nt][1]);
            *reinterpret_cast<float2*>(&g_h1pre[(size_t)(row + 8) * HH + col]) =
                make_float2(acc1[mt][nt][2], acc1[mt][nt][3]);
            *reinterpret_cast<float2*>(&g_t2pre[(size_t)row * HH + col]) =
                make_float2(acc2[mt][nt][0], acc2[mt][nt][1]);
            *reinterpret_cast<float2*>(&g_t2pre[(size_t)(row + 8) * HH + col]) =
                make_float2(acc2[mt][nt][2], acc2[mt][nt][3]);
        }
    }
}

// ======= accumulating GEMM: t2pre = (t2pre + h1 @ W2b^T) * dinv (K=128) =======
__global__ void __launch_bounds__(256, 1) k_mma_h(const float* __restrict__ A) {
    extern __shared__ char sm[];
    const uint32_t sb = smem_to_u32(sm);
    const int tid = threadIdx.x;
    const int lane = tid & 31;
    const int wid = tid >> 5;
    const int wM = (wid & 1) * 64;
    const int wN = (wid >> 1) * 32;
    const int rowBase = blockIdx.x * 128;

    float acc[4][4][4];
#pragma unroll
    for (int i = 0; i < 4; i++)
#pragma unroll
        for (int j = 0; j < 4; j++)
#pragma unroll
            for (int q = 0; q < 4; q++) acc[i][j][q] = 0.0f;

    cpA(sb, A, HH, rowBase, 0, tid);
#pragma unroll
    for (int it = 0; it < 4; it++) {
        int u = it * 256 + tid;
        int n = u >> 3, ch = u & 7;
        size_t go = (size_t)n * HH + ch * 8;
        int off = swoff(ch >> 1, n, ch & 1);
        cp16(sb + BB0_OFF + off, g_w2bt + go);
    }
    CP_COMMIT();

    for (int kc = 0; kc < 2; kc++) {
        CP_WAIT0();
        __syncthreads();
        convert_AR(sm, tid);
        __syncthreads();

        if (kc == 0) {
            cpA(sb, A, HH, rowBase, 1, tid);
            uint32_t bdst = sb + BB0_OFF + TILE;
#pragma unroll
            for (int it = 0; it < 4; it++) {
                int u = it * 256 + tid;
                int n = u >> 3, ch = u & 7;
                size_t go = (size_t)n * HH + 64 + ch * 8;
                int off = swoff(ch >> 1, n, ch & 1);
                cp16(bdst + off, g_w2bt + go);
            }
            CP_COMMIT();
        }

        uint32_t bbB = sb + BB0_OFF + (uint32_t)(kc * TILE);
#pragma unroll
        for (int ks = 0; ks < 4; ks++) {
            uint32_t ah[4][4];
            load_a_frags1(sb + ABF_OFF, ks, wM, lane, ah);
            uint32_t bh[4][2];
            load_b_frags(bbB, ks, wN, lane, bh);
#pragma unroll
            for (int mt = 0; mt < 4; mt++)
#pragma unroll
                for (int nt = 0; nt < 4; nt++)
                    mma16816(acc[mt][nt], ah[mt], bh[nt]);
        }
    }

#pragma unroll
    for (int mt = 0; mt < 4; mt++) {
        int row = rowBase + wM + mt * 16 + (lane >> 2);
        float d0 = __ldg(&g_dinv[row]);
        float d1 = __ldg(&g_dinv[row + 8]);
#pragma unroll
        for (int nt = 0; nt < 4; nt++) {
            int col = wN + nt * 8 + (lane & 3) * 2;
            float2* p0 = reinterpret_cast<float2*>(&g_t2pre[(size_t)row * HH + col]);
            float2* p1 = reinterpret_cast<float2*>(&g_t2pre[(size_t)(row + 8) * HH + col]);
            float2 e0 = *p0, e1 = *p1;
            // write prescaled by dinv[row] -> prop2 inner loop needs no weights
            *p0 = make_float2((acc[mt][nt][0] + e0.x) * d0, (acc[mt][nt][1] + e0.y) * d0);
            *p1 = make_float2((acc[mt][nt][2] + e1.x) * d1, (acc[mt][nt][3] + e1.y) * d1);
        }
    }
}

// ---------------- weight prep: transpose to fp16 ----------------
__global__ void k_wprep(const float* __restrict__ W1, const float* __restrict__ W2) {
    int t = blockIdx.x * blockDim.x + threadIdx.x;
    if (t >= HH * FF) return;
    int h = t / FF, k = t % FF;
    g_w1t[t]  = __float2half_rn(W1[(size_t)k * HH + h]);
    g_w2at[t] = __float2half_rn(W2[(size_t)k * HH + h]);
    if (t < HH * HH) {
        int h2 = t / HH, k2 = t % HH;
        g_w2bt[t] = __float2half_rn(W2[(size_t)(FF + k2) * HH + h2]);
    }
}

// ---------------- degree / CSR build ----------------
__global__ void k_zero_cnt() {
    int i = blockIdx.x * blockDim.x + threadIdx.x;
    if (i < NN) g_cnt[i] = 0;
    if (i < BB * HH) { g_pool1i[i] = 0; g_pool2u[i] = 0u; }
}

__global__ void k_deg_count(const int* __restrict__ ei) {
    int t = blockIdx.x * blockDim.x + threadIdx.x;
    if (t < 2 * EE) atomicAdd(&g_cnt[__ldg(&ei[t])], 1);
}

// scan1 with fused deg_fin (dinv + cursor init)
__global__ void k_scan1() {
    __shared__ int sh[256];
    int tid = threadIdx.x;
    int i = blockIdx.x * 256 + tid;
    int v = g_cnt[i];
    g_dinv[i] = rsqrtf((float)v + 1.0f);   // +1 self loop
    g_cursor[i] = 0;
    sh[tid] = v;
    __syncthreads();
#pragma unroll
    for (int o = 1; o < 256; o <<= 1) {
        int t = (tid >= o) ? sh[tid - o] : 0;
        __syncthreads();
        sh[tid] += t;
        __syncthreads();
    }
    g_rowptr[i] = sh[tid] - v;
    if (tid == 255) g_blksum[blockIdx.x] = sh[255];
}

__global__ void k_scan2() {
    __shared__ int sh[512];
    int tid = threadIdx.x;
    int v = g_blksum[tid];
    sh[tid] = v;
    __syncthreads();
#pragma unroll
    for (int o = 1; o < 512; o <<= 1) {
        int t = (tid >= o) ? sh[tid - o] : 0;
        __syncthreads();
        sh[tid] += t;
        __syncthreads();
    }
    g_blksum[tid] = sh[tid] - v;
}

__global__ void k_scan3() {
    int i = blockIdx.x * 256 + threadIdx.x;
    g_rowptr[i] += g_blksum[blockIdx.x];
    if (i == NN - 1) g_rowptr[NN] = 2 * EE;
}

__global__ void k_fill(const int* __restrict__ ei) {
    int t = blockIdx.x * blockDim.x + threadIdx.x;
    if (t >= 2 * EE) return;
    int src = __ldg(&ei[t]);
    int dst = (t < EE) ? __ldg(&ei[t + EE]) : __ldg(&ei[t - EE]);
    int pos = g_rowptr[dst] + atomicAdd(&g_cursor[dst], 1);
    g_esrc[pos] = src;
}

// conv1: agg1 = relu(prop + b1); pool1 fused (block max -> global atomicMax).
__global__ void __launch_bounds__(256) k_prop1(const float* __restrict__ h,
                                               float* __restrict__ agg,
                                               const float* __restrict__ bias)
{
    __shared__ int pmax[HH];
    int node = blockIdx.x * 8 + (threadIdx.x >> 5);
    int lane = threadIdx.x & 31;
    if (threadIdx.x < HH) pmax[threadIdx.x] = 0;   // relu => values >= 0
    __syncthreads();

    const float4* h4 = reinterpret_cast<const float4*>(h);
    float dn = __ldg(&g_dinv[node]);
    float4 acc = __ldg(&h4[(size_t)node * 32 + lane]);
    float s2 = dn * dn;
    acc.x *= s2; acc.y *= s2; acc.z *= s2; acc.w *= s2;
    int start = __ldg(&g_rowptr[node]);
    int end   = __ldg(&g_rowptr[node + 1]);
    for (int base = start; base < end; base += 32) {
        int n = min(32, end - base);
        int si = (base + lane < end) ? __ldg(&g_esrc[base + lane]) : 0;
#pragma unroll 4
        for (int j = 0; j < n; j++) {
            int s = __shfl_sync(0xffffffffu, si, j);
            float w = __ldg(&g_dinv[s]) * dn;
            float4 v = __ldg(&h4[(size_t)s * 32 + lane]);
            acc.x = fmaf(v.x, w, acc.x);
            acc.y = fmaf(v.y, w, acc.y);
            acc.z = fmaf(v.z, w, acc.z);
            acc.w = fmaf(v.w, w, acc.w);
        }
    }
    float4 b = *reinterpret_cast<const float4*>(bias + lane * 4);
    acc.x = fmaxf(acc.x + b.x, 0.0f);
    acc.y = fmaxf(acc.y + b.y, 0.0f);
    acc.z = fmaxf(acc.z + b.z, 0.0f);
    acc.w = fmaxf(acc.w + b.w, 0.0f);
    reinterpret_cast<float4*>(agg)[(size_t)node * 32 + lane] = acc;

    atomicMax(&pmax[lane * 4 + 0], __float_as_int(acc.x));
    atomicMax(&pmax[lane * 4 + 1], __float_as_int(acc.y));
    atomicMax(&pmax[lane * 4 + 2], __float_as_int(acc.z));
    atomicMax(&pmax[lane * 4 + 3], __float_as_int(acc.w));
    __syncthreads();
    if (threadIdx.x < HH) {
        int g = (blockIdx.x * 8) >> 8;
        atomicMax(&g_pool1i[g * HH + threadIdx.x], pmax[threadIdx.x]);
    }
}

// conv2: input rows prescaled by dinv (mma_h epilogue) -> plain sum; pool2 fused.
__global__ void __launch_bounds__(256) k_prop2(const float* __restrict__ h)
{
    __shared__ unsigned pmax[HH];
    int node = blockIdx.x * 8 + (threadIdx.x >> 5);
    int lane = threadIdx.x & 31;
    if (threadIdx.x < HH) pmax[threadIdx.x] = 0u;
    __syncthreads();

    const float4* h4 = reinterpret_cast<const float4*>(h);
    float dn = __ldg(&g_dinv[node]);
    float4 acc = __ldg(&h4[(size_t)node * 32 + lane]);   // hs[node] (prescaled)
    int start = __ldg(&g_rowptr[node]);
    int end   = __ldg(&g_rowptr[node + 1]);
    for (int base = start; base < end; base += 32) {
        int n = min(32, end - base);
        int si = (base + lane < end) ? __ldg(&g_esrc[base + lane]) : 0;
#pragma unroll 4
        for (int j = 0; j < n; j++) {
            int s = __shfl_sync(0xffffffffu, si, j);
            float4 v = __ldg(&h4[(size_t)s * 32 + lane]);
            acc.x += v.x; acc.y += v.y; acc.z += v.z; acc.w += v.w;
        }
    }
    // agg2[n] = dn * (hs[n] + sum hs[s])
    acc.x *= dn; acc.y *= dn; acc.z *= dn; acc.w *= dn;
    atomicMax(&pmax[lane * 4 + 0], enc_f(acc.x));
    atomicMax(&pmax[lane * 4 + 1], enc_f(acc.y));
    atomicMax(&pmax[lane * 4 + 2], enc_f(acc.z));
    atomicMax(&pmax[lane * 4 + 3], enc_f(acc.w));
    __syncthreads();
    if (threadIdx.x < HH) {
        int g = (blockIdx.x * 8) >> 8;
        atomicMax(&g_pool2u[g * HH + threadIdx.x], pmax[threadIdx.x]);
    }
}

// ---------------- root transform ----------------
__global__ void k_root(const float* __restrict__ x, const float* __restrict__ Wr,
                       const float* __restrict__ br, float* __restrict__ out)
{
    __shared__ float xs[FF];
    int g = blockIdx.x, j = threadIdx.x;
    const float* xr = x + (size_t)g * NPG * FF;
    for (int k = j; k < FF; k += HH) xs[k] = xr[k];
    __syncthreads();
    float acc = __ldg(&br[j]);
#pragma unroll 8
    for (int k = 0; k < FF; k++)
        acc = fmaf(xs[k], __ldg(&Wr[(size_t)k * HH + j]), acc);
    out[g * HH + j] = fmaxf(acc, 0.0f);
}

// ---------------- head (+ arange tail) ----------------
__global__ void k_head(const float* __restrict__ b2, const float* __restrict__ Wl,
                       const float* __restrict__ bl, float* __restrict__ out, int extra)
{
    if (blockIdx.x >= BB / 8) {
        int t = (blockIdx.x - BB / 8) * 256 + threadIdx.x;
        if (t < extra) out[BB * CC + t] = (float)t;
        return;
    }
    int g = blockIdx.x * 8 + (threadIdx.x >> 5);
    int lane = threadIdx.x & 31;
    float a0 = 0.f, a1 = 0.f, a2 = 0.f, a3 = 0.f;
    for (int k = lane; k < 3 * HH; k += 32) {
        float v;
        if (k < HH)            v = g_root[g * HH + k];
        else if (k < 2 * HH)   v = dec_f(g_pool2u[g * HH + k - HH]) + __ldg(&b2[k - HH]);
        else                   v = __int_as_float(g_pool1i[g * HH + k - 2 * HH]);
        float4 w = __ldg(reinterpret_cast<const float4*>(Wl) + k);
        a0 = fmaf(v, w.x, a0); a1 = fmaf(v, w.y, a1);
        a2 = fmaf(v, w.z, a2); a3 = fmaf(v, w.w, a3);
    }
#pragma unroll
    for (int o = 16; o > 0; o >>= 1) {
        a0 += __shfl_xor_sync(0xffffffffu, a0, o);
        a1 += __shfl_xor_sync(0xffffffffu, a1, o);
        a2 += __shfl_xor_sync(0xffffffffu, a2, o);
        a3 += __shfl_xor_sync(0xffffffffu, a3, o);
    }
    if (lane == 0) {
        float l0 = a0 + __ldg(&bl[0]);
        float l1 = a1 + __ldg(&bl[1]);
        float l2 = a2 + __ldg(&bl[2]);
        float l3 = a3 + __ldg(&bl[3]);
        float m = fmaxf(fmaxf(l0, l1), fmaxf(l2, l3));
        float s = expf(l0 - m) + expf(l1 - m) + expf(l2 - m) + expf(l3 - m);
        float lse = m + logf(s);
        out[g * CC + 0] = l0 - lse;
        out[g * CC + 1] = l1 - lse;
        out[g * CC + 2] = l2 - lse;
        out[g * CC + 3] = l3 - lse;
    }
}

// ---------------- launch: forked-graph schedule (R14 topology) ----------------
extern "C" void kernel_launch(void* const* d_in, const int* in_sizes, int n_in,
                              void* d_out, int out_size)
{
    const float* x  = (const float*)d_in[0];
    const int*   ei = (const int*)d_in[1];
    const float* W1 = (const float*)d_in[3];
    const float* b1 = (const float*)d_in[4];
    const float* W2 = (const float*)d_in[5];
    const float* b2 = (const float*)d_in[6];
    const float* Wr = (const float*)d_in[7];
    const float* br = (const float*)d_in[8];
    const float* Wl = (const float*)d_in[9];
    const float* bl = (const float*)d_in[10];
    float* out = (float*)d_out;

    float *h1pre, *t2pre, *agg1, *root;
    cudaGetSymbolAddress((void**)&h1pre, g_h1pre);
    cudaGetSymbolAddress((void**)&t2pre, g_t2pre);
    cudaGetSymbolAddress((void**)&agg1,  g_agg1);
    cudaGetSymbolAddress((void**)&root,  g_root);

    cudaFuncSetAttribute(k_mma_x2, cudaFuncAttributeMaxDynamicSharedMemorySize, X_SMEM);
    cudaFuncSetAttribute(k_mma_h,  cudaFuncAttributeMaxDynamicSharedMemorySize, H_SMEM);

    // Side stream + events (host objects leaked deliberately; replays never
    // re-run host code).
    cudaStream_t s2;
    cudaStreamCreateWithFlags(&s2, cudaStreamNonBlocking);
    cudaEvent_t evFork, evB;
    cudaEventCreateWithFlags(&evFork, cudaEventDisableTiming);
    cudaEventCreateWithFlags(&evB,    cudaEventDisableTiming);

    // fork
    cudaEventRecord(evFork, 0);
    cudaStreamWaitEvent(s2, evFork, 0);

    // Branch B (s2): weight prep -> big dual GEMM  (tensor/DRAM-bound)
    k_wprep<<<(HH * FF + 255) / 256, 256, 0, s2>>>(W1, W2);
    k_mma_x2<<<NN / 128, 256, X_SMEM, s2>>>(x);
    cudaEventRecord(evB, s2);

    // Branch A (stream 0): CSR build + root + pool init (memory-bound)
    k_zero_cnt<<<NN / 256, 256>>>();
    k_deg_count<<<(2 * EE) / 256, 256>>>(ei);
    k_scan1<<<512, 256>>>();
    k_scan2<<<1, 512>>>();
    k_scan3<<<512, 256>>>();
    k_fill<<<(2 * EE) / 256, 256>>>(ei);
    k_root<<<BB, HH>>>(x, Wr, br, root);

    // join: prop1 needs CSR (stream 0) + h1pre (evB)
    cudaStreamWaitEvent(0, evB, 0);

    // conv1 propagate + bias/relu + fused pool1
    k_prop1<<<NN / 8, 256>>>(h1pre, agg1, b1);

    // t2pre = (t2pre + h1 @ W2b) * dinv
    k_mma_h<<<NN / 128, 256, H_SMEM>>>(agg1);

    // conv2 propagate (prescaled input) + fused pool2
    k_prop2<<<NN / 8, 256>>>(t2pre);

    // head + tail
    int extra = out_size - BB * CC;
    int tailBlocks = (extra > 0) ? (extra + 255) / 256 : 0;
    k_head<<<BB / 8 + tailBlocks, 256>>>(b2, Wl, bl, out, extra);
}